// round 2
// baseline (speedup 1.0000x reference)
#include <cuda_runtime.h>
#include <math.h>

#define BB 2
#define SS 2048
#define DM 1024
#define HH 16
#define DK 64
#define BSROWS (BB*SS)      // 4096
#define QKVN (3*DM)         // 3072

// Scratch (allocation-free rule: __device__ globals)
__device__ float g_qkv[(size_t)BSROWS*QKVN];   // [B*S, 3072]
__device__ float g_q[(size_t)BB*HH*SS*DK];     // [B*H, S, 64] (pre-scaled by 1/8)
__device__ float g_k[(size_t)BB*HH*SS*DK];
__device__ float g_v[(size_t)BB*HH*SS*DK];
__device__ float g_att[(size_t)BSROWS*DM];     // [B*S, 1024]

// ---------------------------------------------------------------------------
// C[M,N] = A[M,K] @ W[N,K]^T (row-major). 128x128 tile, BK=16, 256 threads,
// 8x8 microtile. A/W staged transposed in smem so the k-loop reads float4.
// ---------------------------------------------------------------------------
__device__ __forceinline__
void gemm_bt_body(const float* __restrict__ A, const float* __restrict__ W,
                  float* __restrict__ C, int N, int K) {
    __shared__ float As[16][128];
    __shared__ float Bs[16][128];

    const int tid = threadIdx.x;
    const int m0 = blockIdx.y * 128;
    const int n0 = blockIdx.x * 128;
    const int tx = tid & 15;        // 0..15 -> N (8 cols each)
    const int ty = tid >> 4;        // 0..15 -> M (8 rows each)
    const int lr = tid >> 1;        // 0..127 load row
    const int lc = (tid & 1) * 8;   // 0 or 8: k-offset

    float acc[8][8];
#pragma unroll
    for (int i = 0; i < 8; i++)
#pragma unroll
        for (int j = 0; j < 8; j++) acc[i][j] = 0.0f;

    for (int k0 = 0; k0 < K; k0 += 16) {
        {
            const float* ap = A + (size_t)(m0 + lr) * K + k0 + lc;
            float4 a0 = *(const float4*)(ap);
            float4 a1 = *(const float4*)(ap + 4);
            As[lc + 0][lr] = a0.x; As[lc + 1][lr] = a0.y;
            As[lc + 2][lr] = a0.z; As[lc + 3][lr] = a0.w;
            As[lc + 4][lr] = a1.x; As[lc + 5][lr] = a1.y;
            As[lc + 6][lr] = a1.z; As[lc + 7][lr] = a1.w;
            const float* bp = W + (size_t)(n0 + lr) * K + k0 + lc;
            float4 b0 = *(const float4*)(bp);
            float4 b1 = *(const float4*)(bp + 4);
            Bs[lc + 0][lr] = b0.x; Bs[lc + 1][lr] = b0.y;
            Bs[lc + 2][lr] = b0.z; Bs[lc + 3][lr] = b0.w;
            Bs[lc + 4][lr] = b1.x; Bs[lc + 5][lr] = b1.y;
            Bs[lc + 6][lr] = b1.z; Bs[lc + 7][lr] = b1.w;
        }
        __syncthreads();

#pragma unroll
        for (int kk = 0; kk < 16; kk++) {
            float ar[8], br[8];
            float4 a0 = *(const float4*)&As[kk][ty * 8];
            float4 a1 = *(const float4*)&As[kk][ty * 8 + 4];
            ar[0] = a0.x; ar[1] = a0.y; ar[2] = a0.z; ar[3] = a0.w;
            ar[4] = a1.x; ar[5] = a1.y; ar[6] = a1.z; ar[7] = a1.w;
            float4 b0 = *(const float4*)&Bs[kk][tx * 8];
            float4 b1 = *(const float4*)&Bs[kk][tx * 8 + 4];
            br[0] = b0.x; br[1] = b0.y; br[2] = b0.z; br[3] = b0.w;
            br[4] = b1.x; br[5] = b1.y; br[6] = b1.z; br[7] = b1.w;
#pragma unroll
            for (int i = 0; i < 8; i++)
#pragma unroll
                for (int j = 0; j < 8; j++)
                    acc[i][j] = fmaf(ar[i], br[j], acc[i][j]);
        }
        __syncthreads();
    }

#pragma unroll
    for (int i = 0; i < 8; i++) {
        float* cp = C + (size_t)(m0 + ty * 8 + i) * N + n0 + tx * 8;
        *(float4*)(cp)     = make_float4(acc[i][0], acc[i][1], acc[i][2], acc[i][3]);
        *(float4*)(cp + 4) = make_float4(acc[i][4], acc[i][5], acc[i][6], acc[i][7]);
    }
}

__global__ __launch_bounds__(256)
void gemm_qkv_kernel(const float* __restrict__ x, const float* __restrict__ qkv_w) {
    gemm_bt_body(x, qkv_w, g_qkv, QKVN, DM);
}

__global__ __launch_bounds__(256)
void gemm_out_kernel(const float* __restrict__ out_w, float* __restrict__ out) {
    gemm_bt_body(g_att, out_w, out, DM, DM);
}

// ---------------------------------------------------------------------------
// RoPE + split/transpose: g_qkv [B,S,3,H,DK] -> g_q/g_k/g_v [B*H, S, DK]
// q is pre-scaled by 1/sqrt(DK) = 0.125
// ---------------------------------------------------------------------------
__global__ void rope_split_kernel(const int* __restrict__ pos) {
    int idx = blockIdx.x * blockDim.x + threadIdx.x;
    const int total = BB * SS * HH * (DK / 2);
    if (idx >= total) return;

    int i = idx & 31;                // pair index 0..31
    int h = (idx >> 5) & (HH - 1);   // 0..15
    int s = (idx >> 9) & (SS - 1);   // 0..2047
    int b = idx >> 20;               // 0..1

    int p = pos[b * SS + s];
    float inv_freq = expf(-((float)(2 * i) / (float)DK) * logf(10000.0f));
    float ang = (float)p * inv_freq;
    float c = cosf(ang);
    float sn = sinf(ang);

    const float* base = g_qkv + (size_t)(b * SS + s) * QKVN;
    int col = h * DK + 2 * i;
    float q1 = base[col],          q2 = base[col + 1];
    float k1 = base[DM + col],     k2 = base[DM + col + 1];
    float v1 = base[2 * DM + col], v2 = base[2 * DM + col + 1];

    size_t o = ((size_t)(b * HH + h) * SS + s) * DK + 2 * i;
    const float qs = 0.125f;
    g_q[o]     = (q1 * c - q2 * sn) * qs;
    g_q[o + 1] = (q1 * sn + q2 * c) * qs;
    g_k[o]     = k1 * c - k2 * sn;
    g_k[o + 1] = k1 * sn + k2 * c;
    g_v[o]     = v1;
    g_v[o + 1] = v2;
}

// ---------------------------------------------------------------------------
// Causal flash attention, fp32. One block = (bh, 64-query tile), 64 threads,
// one thread per query row. K/V tiles + per-row scores staged in smem (48 KB).
// Writes [B, S, H*DK] so the out-projection sees [B*S, DM] directly.
// ---------------------------------------------------------------------------
__global__ __launch_bounds__(64)
void attn_kernel() {
    __shared__ float Ks[64 * 64];
    __shared__ float Vs[64 * 64];
    __shared__ float Sc[64][64];   // [j][r] — conflict-free (r = lane)

    const int bh = blockIdx.y;
    const int qt = blockIdx.x;
    const int r  = threadIdx.x;
    const int qi = qt * 64 + r;

    const float* Qb = g_q + (size_t)bh * SS * DK;
    const float* Kb = g_k + (size_t)bh * SS * DK;
    const float* Vb = g_v + (size_t)bh * SS * DK;

    float qreg[DK];
    {
        const float4* qsrc = (const float4*)(Qb + (size_t)qi * DK);
#pragma unroll
        for (int d4 = 0; d4 < 16; d4++) {
            float4 v = qsrc[d4];
            qreg[4 * d4 + 0] = v.x; qreg[4 * d4 + 1] = v.y;
            qreg[4 * d4 + 2] = v.z; qreg[4 * d4 + 3] = v.w;
        }
    }

    float acc[DK];
#pragma unroll
    for (int d = 0; d < DK; d++) acc[d] = 0.0f;
    float m = -INFINITY, l = 0.0f;

    for (int j0 = 0; j0 <= qt * 64; j0 += 64) {
        // cooperative, coalesced tile load (tiles are contiguous 16 KB chunks)
        {
            const float4* ksrc = (const float4*)(Kb + (size_t)j0 * DK);
            const float4* vsrc = (const float4*)(Vb + (size_t)j0 * DK);
            float4* kd = (float4*)Ks;
            float4* vd = (float4*)Vs;
            for (int t = r; t < 1024; t += 64) { kd[t] = ksrc[t]; vd[t] = vsrc[t]; }
        }
        __syncthreads();

        const bool diag = (j0 == qt * 64);
        float tmax = m;
        for (int j = 0; j < 64; j++) {
            const float4* kr = (const float4*)(Ks + j * 64);
            float sum = 0.0f;
#pragma unroll
            for (int d4 = 0; d4 < 16; d4++) {
                float4 k4 = kr[d4];
                sum = fmaf(qreg[4 * d4 + 0], k4.x, sum);
                sum = fmaf(qreg[4 * d4 + 1], k4.y, sum);
                sum = fmaf(qreg[4 * d4 + 2], k4.z, sum);
                sum = fmaf(qreg[4 * d4 + 3], k4.w, sum);
            }
            if (diag && (j0 + j > qi)) sum = -INFINITY;
            Sc[j][r] = sum;
            tmax = fmaxf(tmax, sum);
        }

        float scale = __expf(m - tmax);   // m=-inf first time -> 0
        m = tmax;
        l *= scale;
#pragma unroll
        for (int d = 0; d < DK; d++) acc[d] *= scale;

        for (int j = 0; j < 64; j++) {
            float p = __expf(Sc[j][r] - m);
            l += p;
            const float4* vr = (const float4*)(Vs + j * 64);
#pragma unroll
            for (int d4 = 0; d4 < 16; d4++) {
                float4 v4 = vr[d4];
                acc[4 * d4 + 0] = fmaf(p, v4.x, acc[4 * d4 + 0]);
                acc[4 * d4 + 1] = fmaf(p, v4.y, acc[4 * d4 + 1]);
                acc[4 * d4 + 2] = fmaf(p, v4.z, acc[4 * d4 + 2]);
                acc[4 * d4 + 3] = fmaf(p, v4.w, acc[4 * d4 + 3]);
            }
        }
        __syncthreads();
    }

    const float inv = 1.0f / l;
    const int b = bh / HH;
    const int h = bh % HH;
    float* dst = g_att + ((size_t)b * SS + qi) * DM + h * DK;
#pragma unroll
    for (int d4 = 0; d4 < 16; d4++) {
        float4 v = make_float4(acc[4 * d4 + 0] * inv, acc[4 * d4 + 1] * inv,
                               acc[4 * d4 + 2] * inv, acc[4 * d4 + 3] * inv);
        *(float4*)(dst + 4 * d4) = v;
    }
}

// ---------------------------------------------------------------------------
extern "C" void kernel_launch(void* const* d_in, const int* in_sizes, int n_in,
                              void* d_out, int out_size) {
    const float* x     = (const float*)d_in[0];
    const int*   pos   = (const int*)d_in[1];
    const float* qkv_w = (const float*)d_in[2];
    const float* out_w = (const float*)d_in[3];
    float* out = (float*)d_out;

    // 1) QKV projection: g_qkv[4096,3072] = x[4096,1024] @ qkv_w[3072,1024]^T
    {
        dim3 grid(QKVN / 128, BSROWS / 128);
        gemm_qkv_kernel<<<grid, 256>>>(x, qkv_w);
    }
    // 2) RoPE + split/transpose
    {
        int total = BB * SS * HH * (DK / 2);
        rope_split_kernel<<<(total + 255) / 256, 256>>>(pos);
    }
    // 3) Causal flash attention
    {
        dim3 grid(SS / 64, BB * HH);
        attn_kernel<<<grid, 64>>>();
    }
    // 4) Output projection: out[4096,1024] = g_att @ out_w[1024,1024]^T
    {
        dim3 grid(DM / 128, BSROWS / 128);
        gemm_out_kernel<<<grid, 256>>>(out_w, out);
    }
}

// round 5
// speedup vs baseline: 1.5670x; 1.5670x over previous
#include <cuda_runtime.h>
#include <cuda_bf16.h>
#include <math.h>
#include <stdint.h>

#define BB 2
#define SS 2048
#define DM 1024
#define HH 16
#define DK 64
#define BSROWS (BB*SS)      // 4096
#define QKVN (3*DM)         // 3072

// Scratch (allocation-free rule: __device__ globals)
__device__ float g_qkv[(size_t)BSROWS*QKVN];   // [B*S, 3072]
__device__ float g_q[(size_t)BB*HH*SS*DK];     // [B*H, S, 64] (pre-scaled by 1/8)
__device__ float g_k[(size_t)BB*HH*SS*DK];
__device__ float g_v[(size_t)BB*HH*SS*DK];
__device__ float g_att[(size_t)BSROWS*DM];     // [B*S, 1024]

// ===========================================================================
// mma.sync helpers (sm_80+ path — tcgen05 unavailable: ptxas target is sm_100
// without the 'a' feature suffix)
// ===========================================================================
__device__ __forceinline__ uint32_t smem_u32(const void* p) {
    uint32_t a;
    asm("{ .reg .u64 t; cvta.to.shared.u64 t, %1; cvt.u32.u64 %0, t; }" : "=r"(a) : "l"(p));
    return a;
}

__device__ __forceinline__ void ldsm_x4(uint32_t* r, uint32_t addr) {
    asm volatile("ldmatrix.sync.aligned.m8n8.x4.shared.b16 {%0,%1,%2,%3}, [%4];"
                 : "=r"(r[0]), "=r"(r[1]), "=r"(r[2]), "=r"(r[3]) : "r"(addr));
}
// B operand: smem tile is [n][k] row-major (k contiguous) == col-major KxN,
// which is exactly what mma row.col wants -> NO .trans (R4 bug: had .trans)
__device__ __forceinline__ void ldsm_x2(uint32_t* r, uint32_t addr) {
    asm volatile("ldmatrix.sync.aligned.m8n8.x2.shared.b16 {%0,%1}, [%2];"
                 : "=r"(r[0]), "=r"(r[1]) : "r"(addr));
}
__device__ __forceinline__ void mma16816(float* d, const uint32_t* a, const uint32_t* b) {
    asm volatile("mma.sync.aligned.m16n8k16.row.col.f32.bf16.bf16.f32 "
                 "{%0,%1,%2,%3}, {%4,%5,%6,%7}, {%8,%9}, {%0,%1,%2,%3};"
                 : "+f"(d[0]), "+f"(d[1]), "+f"(d[2]), "+f"(d[3])
                 : "r"(a[0]), "r"(a[1]), "r"(a[2]), "r"(a[3]), "r"(b[0]), "r"(b[1]));
}

// ===========================================================================
// bf16x3 GEMM via mma.sync: C[M,N] = A[M,K] @ W[N,K]^T, fp32 in/out.
// CTA tile 128x128, 8 warps (64x32 each), K-chunk 32, double-buffered smem.
// smem rows padded to 40 bf16 (80B) -> conflict-free ldmatrix.
// ===========================================================================
#define KC 32
#define LDAS 40                         // padded row stride (bf16 elements)
#define TILE_HL (128 * LDAS * 2)        // 10240 B: one 128x32 bf16 tile
#define STAGE_B (4 * TILE_HL)           // Ahi, Alo, Bhi, Blo = 40960 B
#define GEMM_SMEM (2 * STAGE_B)         // 81920 B

#define OFF_AHI 0
#define OFF_ALO TILE_HL
#define OFF_BHI (2*TILE_HL)
#define OFF_BLO (3*TILE_HL)

__device__ __forceinline__ uint32_t bf2u(__nv_bfloat16 a, __nv_bfloat16 b) {
    __nv_bfloat162 t; t.x = a; t.y = b;
    return *reinterpret_cast<uint32_t*>(&t);
}

// convert a float4 into hi/lo bf16x2 pairs
__device__ __forceinline__ void cvt_hl(float4 v, uint2& hi, uint2& lo) {
    __nv_bfloat16 h0 = __float2bfloat16_rn(v.x);
    __nv_bfloat16 h1 = __float2bfloat16_rn(v.y);
    __nv_bfloat16 h2 = __float2bfloat16_rn(v.z);
    __nv_bfloat16 h3 = __float2bfloat16_rn(v.w);
    __nv_bfloat16 l0 = __float2bfloat16_rn(v.x - __bfloat162float(h0));
    __nv_bfloat16 l1 = __float2bfloat16_rn(v.y - __bfloat162float(h1));
    __nv_bfloat16 l2 = __float2bfloat16_rn(v.z - __bfloat162float(h2));
    __nv_bfloat16 l3 = __float2bfloat16_rn(v.w - __bfloat162float(h3));
    hi = make_uint2(bf2u(h0, h1), bf2u(h2, h3));
    lo = make_uint2(bf2u(l0, l1), bf2u(l2, l3));
}

__device__ __forceinline__
void gemm_tc_body(const float* __restrict__ A, const float* __restrict__ W,
                  float* __restrict__ C, int K, int N) {
    extern __shared__ char smem[];
    const uint32_t sbase = smem_u32(smem);
    const int tid  = threadIdx.x;
    const int wid  = tid >> 5;
    const int lane = tid & 31;
    const int m0 = blockIdx.y * 128;
    const int n0 = blockIdx.x * 128;
    const int wm = wid & 1;          // 0/1 -> m offset 64*wm
    const int wn = wid >> 1;         // 0..3 -> n offset 32*wn

    // per-thread load coords: 4 float4 per tile (A and B each)
    int lrow[4], lkq[4];
#pragma unroll
    for (int it = 0; it < 4; it++) {
        int f = it * 256 + tid;
        lrow[it] = f >> 3;
        lkq[it]  = (f & 7) * 4;
    }

    // ldmatrix lane addressing (element offsets)
    const int arow = (lane & 7) + ((lane >> 3) & 1) * 8;
    const int acol = (lane >> 4) * 8;
    const int bl   = lane & 15;
    const int brow = bl & 7;          // n row within 8
    const int bk   = (bl >> 3) * 8;   // k offset 0 or 8

    float acc[4][4][4];
#pragma unroll
    for (int mi = 0; mi < 4; mi++)
#pragma unroll
        for (int ni = 0; ni < 4; ni++)
#pragma unroll
            for (int q = 0; q < 4; q++) acc[mi][ni][q] = 0.0f;

    const int nch = K / KC;
    float4 pa[4], pb[4];

    // prologue: load chunk 0 into regs, store to stage 0
#pragma unroll
    for (int it = 0; it < 4; it++) {
        pa[it] = *(const float4*)(A + (size_t)(m0 + lrow[it]) * K + lkq[it]);
        pb[it] = *(const float4*)(W + (size_t)(n0 + lrow[it]) * K + lkq[it]);
    }
    {
        char* stg = smem;
#pragma unroll
        for (int it = 0; it < 4; it++) {
            uint32_t off = (lrow[it] * LDAS + lkq[it]) * 2;
            uint2 hi, lo;
            cvt_hl(pa[it], hi, lo);
            *(uint2*)(stg + OFF_AHI + off) = hi;
            *(uint2*)(stg + OFF_ALO + off) = lo;
            cvt_hl(pb[it], hi, lo);
            *(uint2*)(stg + OFF_BHI + off) = hi;
            *(uint2*)(stg + OFF_BLO + off) = lo;
        }
    }
    __syncthreads();

    for (int c = 0; c < nch; c++) {
        // prefetch next chunk into registers (hide gmem latency under mma)
        if (c + 1 < nch) {
            const int k0 = (c + 1) * KC;
#pragma unroll
            for (int it = 0; it < 4; it++) {
                pa[it] = *(const float4*)(A + (size_t)(m0 + lrow[it]) * K + k0 + lkq[it]);
                pb[it] = *(const float4*)(W + (size_t)(n0 + lrow[it]) * K + k0 + lkq[it]);
            }
        }

        // compute on stage c&1
        const uint32_t stg = sbase + (c & 1) * STAGE_B;
#pragma unroll
        for (int ks = 0; ks < 2; ks++) {
            uint32_t ah[4][4], al[4][4], bh[4][2], blr[4][2];
#pragma unroll
            for (int mi = 0; mi < 4; mi++) {
                uint32_t eoff = ((wm * 64 + mi * 16 + arow) * LDAS + ks * 16 + acol) * 2;
                ldsm_x4(ah[mi], stg + OFF_AHI + eoff);
                ldsm_x4(al[mi], stg + OFF_ALO + eoff);
            }
#pragma unroll
            for (int ni = 0; ni < 4; ni++) {
                uint32_t eoff = ((wn * 32 + ni * 8 + brow) * LDAS + ks * 16 + bk) * 2;
                ldsm_x2(bh[ni],  stg + OFF_BHI + eoff);
                ldsm_x2(blr[ni], stg + OFF_BLO + eoff);
            }
#pragma unroll
            for (int mi = 0; mi < 4; mi++)
#pragma unroll
                for (int ni = 0; ni < 4; ni++) {
                    mma16816(acc[mi][ni], ah[mi], bh[ni]);
                    mma16816(acc[mi][ni], ah[mi], blr[ni]);
                    mma16816(acc[mi][ni], al[mi], bh[ni]);
                }
        }
        __syncthreads();

        // store prefetched chunk into the other stage
        if (c + 1 < nch) {
            char* stg2 = smem + ((c + 1) & 1) * STAGE_B;
#pragma unroll
            for (int it = 0; it < 4; it++) {
                uint32_t off = (lrow[it] * LDAS + lkq[it]) * 2;
                uint2 hi, lo;
                cvt_hl(pa[it], hi, lo);
                *(uint2*)(stg2 + OFF_AHI + off) = hi;
                *(uint2*)(stg2 + OFF_ALO + off) = lo;
                cvt_hl(pb[it], hi, lo);
                *(uint2*)(stg2 + OFF_BHI + off) = hi;
                *(uint2*)(stg2 + OFF_BLO + off) = lo;
            }
            __syncthreads();
        }
    }

    // epilogue: write accumulators
    const int crow = lane >> 2;
    const int ccol = (lane & 3) * 2;
#pragma unroll
    for (int mi = 0; mi < 4; mi++) {
        const size_t r0 = (size_t)(m0 + wm * 64 + mi * 16 + crow);
#pragma unroll
        for (int ni = 0; ni < 4; ni++) {
            const int cc = n0 + wn * 32 + ni * 8 + ccol;
            *(float2*)(C + r0 * N + cc)       = make_float2(acc[mi][ni][0], acc[mi][ni][1]);
            *(float2*)(C + (r0 + 8) * N + cc) = make_float2(acc[mi][ni][2], acc[mi][ni][3]);
        }
    }
}

__global__ __launch_bounds__(256)
void gemm_qkv_kernel(const float* __restrict__ x, const float* __restrict__ qkv_w) {
    gemm_tc_body(x, qkv_w, g_qkv, DM, QKVN);
}
__global__ __launch_bounds__(256)
void gemm_out_kernel(const float* __restrict__ out_w, float* __restrict__ out) {
    gemm_tc_body(g_att, out_w, out, DM, DM);
}

// ===========================================================================
// RoPE + split/transpose: g_qkv [B,S,3,H,DK] -> g_q/g_k/g_v [B*H, S, DK]
// q pre-scaled by 1/sqrt(DK) = 0.125
// ===========================================================================
__global__ void rope_split_kernel(const int* __restrict__ pos) {
    int idx = blockIdx.x * blockDim.x + threadIdx.x;
    const int total = BB * SS * HH * (DK / 2);
    if (idx >= total) return;

    int i = idx & 31;
    int h = (idx >> 5) & (HH - 1);
    int s = (idx >> 9) & (SS - 1);
    int b = idx >> 20;

    int p = pos[b * SS + s];
    float inv_freq = expf(-((float)(2 * i) / (float)DK) * logf(10000.0f));
    float ang = (float)p * inv_freq;
    float c = cosf(ang);
    float sn = sinf(ang);

    const float* base = g_qkv + (size_t)(b * SS + s) * QKVN;
    int col = h * DK + 2 * i;
    float q1 = base[col],          q2 = base[col + 1];
    float k1 = base[DM + col],     k2 = base[DM + col + 1];
    float v1 = base[2 * DM + col], v2 = base[2 * DM + col + 1];

    size_t o = ((size_t)(b * HH + h) * SS + s) * DK + 2 * i;
    const float qs = 0.125f;
    g_q[o]     = (q1 * c - q2 * sn) * qs;
    g_q[o + 1] = (q1 * sn + q2 * c) * qs;
    g_k[o]     = k1 * c - k2 * sn;
    g_k[o + 1] = k1 * sn + k2 * c;
    g_v[o]     = v1;
    g_v[o + 1] = v2;
}

// ===========================================================================
// Causal flash attention, fp32. Q-tile=128 (128 threads, 1 thread/row),
// K-tile=64. Dynamic smem: Ks 16KB + Vs 16KB + Sc 32KB = 64KB.
// ===========================================================================
#define ATT_SMEM (16384 + 16384 + 32768)

__global__ __launch_bounds__(128)
void attn_kernel() {
    extern __shared__ float asmem[];
    float* Ks = asmem;            // [64][64]
    float* Vs = asmem + 4096;     // [64][64]
    float* Sc = asmem + 8192;     // [64][128]

    const int bh = blockIdx.y;
    const int qt = gridDim.x - 1 - blockIdx.x;   // heavy tiles first
    const int r  = threadIdx.x;
    const int qi = qt * 128 + r;

    const float* Qb = g_q + (size_t)bh * SS * DK;
    const float* Kb = g_k + (size_t)bh * SS * DK;
    const float* Vb = g_v + (size_t)bh * SS * DK;

    float qreg[DK];
    {
        const float4* qsrc = (const float4*)(Qb + (size_t)qi * DK);
#pragma unroll
        for (int d4 = 0; d4 < 16; d4++) {
            float4 v = qsrc[d4];
            qreg[4 * d4 + 0] = v.x; qreg[4 * d4 + 1] = v.y;
            qreg[4 * d4 + 2] = v.z; qreg[4 * d4 + 3] = v.w;
        }
    }

    float acc[DK];
#pragma unroll
    for (int d = 0; d < DK; d++) acc[d] = 0.0f;
    float m = -INFINITY, l = 0.0f;

    const int jend = (qt + 1) * 128;
    for (int j0 = 0; j0 < jend; j0 += 64) {
        {
            const float4* ksrc = (const float4*)(Kb + (size_t)j0 * DK);
            const float4* vsrc = (const float4*)(Vb + (size_t)j0 * DK);
            float4* kd = (float4*)Ks;
            float4* vd = (float4*)Vs;
#pragma unroll
            for (int it = 0; it < 8; it++) { int t = r + it * 128; kd[t] = ksrc[t]; vd[t] = vsrc[t]; }
        }
        __syncthreads();

        const bool needmask = (j0 + 63 > qi);
        float tmax = m;
        for (int j = 0; j < 64; j++) {
            const float4* kr = (const float4*)(Ks + j * 64);
            float sum = 0.0f;
#pragma unroll
            for (int d4 = 0; d4 < 16; d4++) {
                float4 k4 = kr[d4];
                sum = fmaf(qreg[4 * d4 + 0], k4.x, sum);
                sum = fmaf(qreg[4 * d4 + 1], k4.y, sum);
                sum = fmaf(qreg[4 * d4 + 2], k4.z, sum);
                sum = fmaf(qreg[4 * d4 + 3], k4.w, sum);
            }
            if (needmask && (j0 + j > qi)) sum = -INFINITY;
            Sc[j * 128 + r] = sum;
            tmax = fmaxf(tmax, sum);
        }

        float scale = __expf(m - tmax);
        m = tmax;
        l *= scale;
#pragma unroll
        for (int d = 0; d < DK; d++) acc[d] *= scale;

        for (int j = 0; j < 64; j++) {
            float p = __expf(Sc[j * 128 + r] - m);
            l += p;
            const float4* vr = (const float4*)(Vs + j * 64);
#pragma unroll
            for (int d4 = 0; d4 < 16; d4++) {
                float4 v4 = vr[d4];
                acc[4 * d4 + 0] = fmaf(p, v4.x, acc[4 * d4 + 0]);
                acc[4 * d4 + 1] = fmaf(p, v4.y, acc[4 * d4 + 1]);
                acc[4 * d4 + 2] = fmaf(p, v4.z, acc[4 * d4 + 2]);
                acc[4 * d4 + 3] = fmaf(p, v4.w, acc[4 * d4 + 3]);
            }
        }
        __syncthreads();
    }

    const float inv = 1.0f / l;
    const int b = bh / HH;
    const int h = bh % HH;
    float* dst = g_att + ((size_t)b * SS + qi) * DM + h * DK;
#pragma unroll
    for (int d4 = 0; d4 < 16; d4++) {
        float4 v = make_float4(acc[4 * d4 + 0] * inv, acc[4 * d4 + 1] * inv,
                               acc[4 * d4 + 2] * inv, acc[4 * d4 + 3] * inv);
        *(float4*)(dst + 4 * d4) = v;
    }
}

// ===========================================================================
extern "C" void kernel_launch(void* const* d_in, const int* in_sizes, int n_in,
                              void* d_out, int out_size) {
    const float* x     = (const float*)d_in[0];
    const int*   pos   = (const int*)d_in[1];
    const float* qkv_w = (const float*)d_in[2];
    const float* out_w = (const float*)d_in[3];
    float* out = (float*)d_out;

    cudaFuncSetAttribute(gemm_qkv_kernel, cudaFuncAttributeMaxDynamicSharedMemorySize, GEMM_SMEM);
    cudaFuncSetAttribute(gemm_out_kernel, cudaFuncAttributeMaxDynamicSharedMemorySize, GEMM_SMEM);
    cudaFuncSetAttribute(attn_kernel,     cudaFuncAttributeMaxDynamicSharedMemorySize, ATT_SMEM);

    // 1) QKV projection: g_qkv[4096,3072] = x @ qkv_w^T   (mma.sync bf16x3)
    gemm_qkv_kernel<<<dim3(QKVN / 128, BSROWS / 128), 256, GEMM_SMEM>>>(x, qkv_w);

    // 2) RoPE + split/transpose
    {
        int total = BB * SS * HH * (DK / 2);
        rope_split_kernel<<<(total + 255) / 256, 256>>>(pos);
    }

    // 3) Causal flash attention
    attn_kernel<<<dim3(SS / 128, BB * HH), 128, ATT_SMEM>>>();

    // 4) Output projection: out = g_att @ out_w^T   (mma.sync bf16x3)
    gemm_out_kernel<<<dim3(DM / 128, BSROWS / 128), 256, GEMM_SMEM>>>(out_w, out);
}

// round 6
// speedup vs baseline: 3.0027x; 1.9163x over previous
#include <cuda_runtime.h>
#include <cuda_bf16.h>
#include <math.h>
#include <stdint.h>

#define BB 2
#define SS 2048
#define DM 1024
#define HH 16
#define DK 64
#define BSROWS (BB*SS)      // 4096
#define QKVN (3*DM)         // 3072

// Scratch (allocation-free rule: __device__ globals)
__device__ float g_qkv[(size_t)BSROWS*QKVN];   // [B*S, 3072]
__device__ float g_q[(size_t)BB*HH*SS*DK];     // [B*H, S, 64] (pre-scaled by 1/8)
__device__ float g_k[(size_t)BB*HH*SS*DK];
__device__ float g_v[(size_t)BB*HH*SS*DK];
__device__ float g_att[(size_t)BSROWS*DM];     // [B*S, 1024]

// ===========================================================================
// mma.sync helpers (sm_80+ path — tcgen05 unavailable on this ptxas target)
// ===========================================================================
__device__ __forceinline__ uint32_t smem_u32(const void* p) {
    uint32_t a;
    asm("{ .reg .u64 t; cvta.to.shared.u64 t, %1; cvt.u32.u64 %0, t; }" : "=r"(a) : "l"(p));
    return a;
}
__device__ __forceinline__ void ldsm_x4(uint32_t* r, uint32_t addr) {
    asm volatile("ldmatrix.sync.aligned.m8n8.x4.shared.b16 {%0,%1,%2,%3}, [%4];"
                 : "=r"(r[0]), "=r"(r[1]), "=r"(r[2]), "=r"(r[3]) : "r"(addr));
}
__device__ __forceinline__ void ldsm_x2(uint32_t* r, uint32_t addr) {
    asm volatile("ldmatrix.sync.aligned.m8n8.x2.shared.b16 {%0,%1}, [%2];"
                 : "=r"(r[0]), "=r"(r[1]) : "r"(addr));
}
__device__ __forceinline__ void ldsm_x2t(uint32_t* r, uint32_t addr) {
    asm volatile("ldmatrix.sync.aligned.m8n8.x2.trans.shared.b16 {%0,%1}, [%2];"
                 : "=r"(r[0]), "=r"(r[1]) : "r"(addr));
}
__device__ __forceinline__ void mma16816(float* d, const uint32_t* a, const uint32_t* b) {
    asm volatile("mma.sync.aligned.m16n8k16.row.col.f32.bf16.bf16.f32 "
                 "{%0,%1,%2,%3}, {%4,%5,%6,%7}, {%8,%9}, {%0,%1,%2,%3};"
                 : "+f"(d[0]), "+f"(d[1]), "+f"(d[2]), "+f"(d[3])
                 : "r"(a[0]), "r"(a[1]), "r"(a[2]), "r"(a[3]), "r"(b[0]), "r"(b[1]));
}

__device__ __forceinline__ uint32_t bf2u(__nv_bfloat16 a, __nv_bfloat16 b) {
    __nv_bfloat162 t; t.x = a; t.y = b;
    return *reinterpret_cast<uint32_t*>(&t);
}
// convert a float4 into hi/lo bf16x2 pairs
__device__ __forceinline__ void cvt_hl(float4 v, uint2& hi, uint2& lo) {
    __nv_bfloat16 h0 = __float2bfloat16_rn(v.x);
    __nv_bfloat16 h1 = __float2bfloat16_rn(v.y);
    __nv_bfloat16 h2 = __float2bfloat16_rn(v.z);
    __nv_bfloat16 h3 = __float2bfloat16_rn(v.w);
    __nv_bfloat16 l0 = __float2bfloat16_rn(v.x - __bfloat162float(h0));
    __nv_bfloat16 l1 = __float2bfloat16_rn(v.y - __bfloat162float(h1));
    __nv_bfloat16 l2 = __float2bfloat16_rn(v.z - __bfloat162float(h2));
    __nv_bfloat16 l3 = __float2bfloat16_rn(v.w - __bfloat162float(h3));
    hi = make_uint2(bf2u(h0, h1), bf2u(h2, h3));
    lo = make_uint2(bf2u(l0, l1), bf2u(l2, l3));
}
__device__ __forceinline__ void split2(float a, float b, uint32_t& hi, uint32_t& lo) {
    __nv_bfloat16 h0 = __float2bfloat16_rn(a);
    __nv_bfloat16 h1 = __float2bfloat16_rn(b);
    __nv_bfloat16 l0 = __float2bfloat16_rn(a - __bfloat162float(h0));
    __nv_bfloat16 l1 = __float2bfloat16_rn(b - __bfloat162float(h1));
    hi = bf2u(h0, h1);
    lo = bf2u(l0, l1);
}

// ===========================================================================
// bf16x3 GEMM via mma.sync: C[M,N] = A[M,K] @ W[N,K]^T, fp32 in/out.
// CTA tile 128x128, 8 warps (64x32 each), K-chunk 32, double-buffered smem.
// ===========================================================================
#define KC 32
#define LDAS 40
#define TILE_HL (128 * LDAS * 2)
#define STAGE_B (4 * TILE_HL)
#define GEMM_SMEM (2 * STAGE_B)

#define OFF_AHI 0
#define OFF_ALO TILE_HL
#define OFF_BHI (2*TILE_HL)
#define OFF_BLO (3*TILE_HL)

__device__ __forceinline__
void gemm_tc_body(const float* __restrict__ A, const float* __restrict__ W,
                  float* __restrict__ C, int K, int N) {
    extern __shared__ char smem[];
    const uint32_t sbase = smem_u32(smem);
    const int tid  = threadIdx.x;
    const int wid  = tid >> 5;
    const int lane = tid & 31;
    const int m0 = blockIdx.y * 128;
    const int n0 = blockIdx.x * 128;
    const int wm = wid & 1;
    const int wn = wid >> 1;

    int lrow[4], lkq[4];
#pragma unroll
    for (int it = 0; it < 4; it++) {
        int f = it * 256 + tid;
        lrow[it] = f >> 3;
        lkq[it]  = (f & 7) * 4;
    }

    const int arow = (lane & 7) + ((lane >> 3) & 1) * 8;
    const int acol = (lane >> 4) * 8;
    const int bl   = lane & 15;
    const int brow = bl & 7;
    const int bk   = (bl >> 3) * 8;

    float acc[4][4][4];
#pragma unroll
    for (int mi = 0; mi < 4; mi++)
#pragma unroll
        for (int ni = 0; ni < 4; ni++)
#pragma unroll
            for (int q = 0; q < 4; q++) acc[mi][ni][q] = 0.0f;

    const int nch = K / KC;
    float4 pa[4], pb[4];

#pragma unroll
    for (int it = 0; it < 4; it++) {
        pa[it] = *(const float4*)(A + (size_t)(m0 + lrow[it]) * K + lkq[it]);
        pb[it] = *(const float4*)(W + (size_t)(n0 + lrow[it]) * K + lkq[it]);
    }
    {
        char* stg = smem;
#pragma unroll
        for (int it = 0; it < 4; it++) {
            uint32_t off = (lrow[it] * LDAS + lkq[it]) * 2;
            uint2 hi, lo;
            cvt_hl(pa[it], hi, lo);
            *(uint2*)(stg + OFF_AHI + off) = hi;
            *(uint2*)(stg + OFF_ALO + off) = lo;
            cvt_hl(pb[it], hi, lo);
            *(uint2*)(stg + OFF_BHI + off) = hi;
            *(uint2*)(stg + OFF_BLO + off) = lo;
        }
    }
    __syncthreads();

    for (int c = 0; c < nch; c++) {
        if (c + 1 < nch) {
            const int k0 = (c + 1) * KC;
#pragma unroll
            for (int it = 0; it < 4; it++) {
                pa[it] = *(const float4*)(A + (size_t)(m0 + lrow[it]) * K + k0 + lkq[it]);
                pb[it] = *(const float4*)(W + (size_t)(n0 + lrow[it]) * K + k0 + lkq[it]);
            }
        }

        const uint32_t stg = sbase + (c & 1) * STAGE_B;
#pragma unroll
        for (int ks = 0; ks < 2; ks++) {
            uint32_t ah[4][4], al[4][4], bh[4][2], blr[4][2];
#pragma unroll
            for (int mi = 0; mi < 4; mi++) {
                uint32_t eoff = ((wm * 64 + mi * 16 + arow) * LDAS + ks * 16 + acol) * 2;
                ldsm_x4(ah[mi], stg + OFF_AHI + eoff);
                ldsm_x4(al[mi], stg + OFF_ALO + eoff);
            }
#pragma unroll
            for (int ni = 0; ni < 4; ni++) {
                uint32_t eoff = ((wn * 32 + ni * 8 + brow) * LDAS + ks * 16 + bk) * 2;
                ldsm_x2(bh[ni],  stg + OFF_BHI + eoff);
                ldsm_x2(blr[ni], stg + OFF_BLO + eoff);
            }
#pragma unroll
            for (int mi = 0; mi < 4; mi++)
#pragma unroll
                for (int ni = 0; ni < 4; ni++) {
                    mma16816(acc[mi][ni], ah[mi], bh[ni]);
                    mma16816(acc[mi][ni], ah[mi], blr[ni]);
                    mma16816(acc[mi][ni], al[mi], bh[ni]);
                }
        }
        __syncthreads();

        if (c + 1 < nch) {
            char* stg2 = smem + ((c + 1) & 1) * STAGE_B;
#pragma unroll
            for (int it = 0; it < 4; it++) {
                uint32_t off = (lrow[it] * LDAS + lkq[it]) * 2;
                uint2 hi, lo;
                cvt_hl(pa[it], hi, lo);
                *(uint2*)(stg2 + OFF_AHI + off) = hi;
                *(uint2*)(stg2 + OFF_ALO + off) = lo;
                cvt_hl(pb[it], hi, lo);
                *(uint2*)(stg2 + OFF_BHI + off) = hi;
                *(uint2*)(stg2 + OFF_BLO + off) = lo;
            }
            __syncthreads();
        }
    }

    const int crow = lane >> 2;
    const int ccol = (lane & 3) * 2;
#pragma unroll
    for (int mi = 0; mi < 4; mi++) {
        const size_t r0 = (size_t)(m0 + wm * 64 + mi * 16 + crow);
#pragma unroll
        for (int ni = 0; ni < 4; ni++) {
            const int cc = n0 + wn * 32 + ni * 8 + ccol;
            *(float2*)(C + r0 * N + cc)       = make_float2(acc[mi][ni][0], acc[mi][ni][1]);
            *(float2*)(C + (r0 + 8) * N + cc) = make_float2(acc[mi][ni][2], acc[mi][ni][3]);
        }
    }
}

__global__ __launch_bounds__(256)
void gemm_qkv_kernel(const float* __restrict__ x, const float* __restrict__ qkv_w) {
    gemm_tc_body(x, qkv_w, g_qkv, DM, QKVN);
}
__global__ __launch_bounds__(256)
void gemm_out_kernel(const float* __restrict__ out_w, float* __restrict__ out) {
    gemm_tc_body(g_att, out_w, out, DM, DM);
}

// ===========================================================================
// RoPE + split/transpose: g_qkv [B,S,3,H,DK] -> g_q/g_k/g_v [B*H, S, DK]
// q pre-scaled by 1/sqrt(DK) = 0.125
// ===========================================================================
__global__ void rope_split_kernel(const int* __restrict__ pos) {
    int idx = blockIdx.x * blockDim.x + threadIdx.x;
    const int total = BB * SS * HH * (DK / 2);
    if (idx >= total) return;

    int i = idx & 31;
    int h = (idx >> 5) & (HH - 1);
    int s = (idx >> 9) & (SS - 1);
    int b = idx >> 20;

    int p = pos[b * SS + s];
    float inv_freq = expf(-((float)(2 * i) / (float)DK) * logf(10000.0f));
    float ang = (float)p * inv_freq;
    float c = cosf(ang);
    float sn = sinf(ang);

    const float* base = g_qkv + (size_t)(b * SS + s) * QKVN;
    int col = h * DK + 2 * i;
    float q1 = base[col],          q2 = base[col + 1];
    float k1 = base[DM + col],     k2 = base[DM + col + 1];
    float v1 = base[2 * DM + col], v2 = base[2 * DM + col + 1];

    size_t o = ((size_t)(b * HH + h) * SS + s) * DK + 2 * i;
    const float qs = 0.125f;
    g_q[o]     = (q1 * c - q2 * sn) * qs;
    g_q[o + 1] = (q1 * sn + q2 * c) * qs;
    g_k[o]     = k1 * c - k2 * sn;
    g_k[o + 1] = k1 * sn + k2 * c;
    g_v[o]     = v1;
    g_v[o + 1] = v2;
}

// ===========================================================================
// Tensor-core causal flash attention (bf16x3). CTA = (bh, 128-q-tile),
// 8 warps x m16 row slabs, kv tiles of 64. Smem: K/V/Q hi+lo, stride 72.
// ===========================================================================
#define AT_LDS 72
#define AT_KHI 0
#define AT_KLO 9216
#define AT_VHI 18432
#define AT_VLO 27648
#define AT_QHI 36864
#define AT_QLO 55296
#define ATT_SMEM 73728

__global__ __launch_bounds__(256)
void attn_tc_kernel() {
    extern __shared__ char smem[];
    const uint32_t sb = smem_u32(smem);
    const int tid  = threadIdx.x;
    const int wid  = tid >> 5;
    const int lane = tid & 31;
    const int bh = blockIdx.y;
    const int qt = gridDim.x - 1 - blockIdx.x;   // heavy tiles first
    const int qbase = qt * 128;

    const float* Qb = g_q + (size_t)bh * SS * DK;
    const float* Kb = g_k + (size_t)bh * SS * DK;
    const float* Vb = g_v + (size_t)bh * SS * DK;

    // ---- load Q tile 128x64 -> hi/lo smem ----
#pragma unroll
    for (int it = 0; it < 8; it++) {
        int f = it * 256 + tid;          // 0..2047 float4s
        int row = f >> 4;
        int c4  = (f & 15) * 4;
        float4 v = *(const float4*)(Qb + (size_t)(qbase + row) * DK + c4);
        uint2 hi, lo;
        cvt_hl(v, hi, lo);
        uint32_t off = (row * AT_LDS + c4) * 2;
        *(uint2*)(smem + AT_QHI + off) = hi;
        *(uint2*)(smem + AT_QLO + off) = lo;
    }
    __syncthreads();

    // ---- per-warp Q fragments (rows wid*16..wid*16+15) ----
    const int arow = (lane & 7) + ((lane >> 3) & 1) * 8;
    const int acol = (lane >> 4) * 8;
    uint32_t qh[4][4], ql[4][4];
#pragma unroll
    for (int ks = 0; ks < 4; ks++) {
        uint32_t eoff = ((wid * 16 + arow) * AT_LDS + ks * 16 + acol) * 2;
        ldsm_x4(qh[ks], sb + AT_QHI + eoff);
        ldsm_x4(ql[ks], sb + AT_QLO + eoff);
    }

    float o[8][4];
#pragma unroll
    for (int ni = 0; ni < 8; ni++)
#pragma unroll
        for (int q = 0; q < 4; q++) o[ni][q] = 0.0f;
    float m0 = -INFINITY, m1 = -INFINITY, l0 = 0.0f, l1 = 0.0f;

    const int g  = lane >> 2;
    const int qq = lane & 3;
    const int row0 = qbase + wid * 16 + g;       // row1 = row0 + 8
    const int warp_maxrow = qbase + wid * 16 + 15;

    const int bl = lane & 15;
    const int brow = bl & 7;
    const int bk = (bl >> 3) * 8;

    const int ntiles = (qt + 1) * 2;
    for (int t = 0; t < ntiles; t++) {
        const int kvb = t * 64;

        // ---- cooperative K/V tile load (64x64 fp32 -> bf16 hi/lo) ----
#pragma unroll
        for (int it = 0; it < 4; it++) {
            int f = it * 256 + tid;      // 0..1023 float4s
            int row = f >> 4;
            int c4  = (f & 15) * 4;
            uint32_t off = (row * AT_LDS + c4) * 2;
            uint2 hi, lo;
            float4 kv4 = *(const float4*)(Kb + (size_t)(kvb + row) * DK + c4);
            cvt_hl(kv4, hi, lo);
            *(uint2*)(smem + AT_KHI + off) = hi;
            *(uint2*)(smem + AT_KLO + off) = lo;
            float4 vv4 = *(const float4*)(Vb + (size_t)(kvb + row) * DK + c4);
            cvt_hl(vv4, hi, lo);
            *(uint2*)(smem + AT_VHI + off) = hi;
            *(uint2*)(smem + AT_VLO + off) = lo;
        }
        __syncthreads();

        if (kvb <= warp_maxrow) {
            // ---- S = Q @ K^T (3-term) ----
            float s[8][4];
#pragma unroll
            for (int ni = 0; ni < 8; ni++)
#pragma unroll
                for (int q = 0; q < 4; q++) s[ni][q] = 0.0f;
#pragma unroll
            for (int ks = 0; ks < 4; ks++) {
#pragma unroll
                for (int ni = 0; ni < 8; ni++) {
                    uint32_t kh[2], kl[2];
                    uint32_t eoff = ((ni * 8 + brow) * AT_LDS + ks * 16 + bk) * 2;
                    ldsm_x2(kh, sb + AT_KHI + eoff);
                    ldsm_x2(kl, sb + AT_KLO + eoff);
                    mma16816(s[ni], qh[ks], kh);
                    mma16816(s[ni], qh[ks], kl);
                    mma16816(s[ni], ql[ks], kh);
                }
            }

            // ---- causal mask ----
            if (kvb + 63 > qbase + wid * 16) {
#pragma unroll
                for (int ni = 0; ni < 8; ni++) {
                    int c = kvb + ni * 8 + qq * 2;
                    if (c     > row0)     s[ni][0] = -INFINITY;
                    if (c + 1 > row0)     s[ni][1] = -INFINITY;
                    if (c     > row0 + 8) s[ni][2] = -INFINITY;
                    if (c + 1 > row0 + 8) s[ni][3] = -INFINITY;
                }
            }

            // ---- online softmax ----
            float t0 = -INFINITY, t1 = -INFINITY;
#pragma unroll
            for (int ni = 0; ni < 8; ni++) {
                t0 = fmaxf(t0, fmaxf(s[ni][0], s[ni][1]));
                t1 = fmaxf(t1, fmaxf(s[ni][2], s[ni][3]));
            }
            t0 = fmaxf(t0, __shfl_xor_sync(0xFFFFFFFF, t0, 1));
            t0 = fmaxf(t0, __shfl_xor_sync(0xFFFFFFFF, t0, 2));
            t1 = fmaxf(t1, __shfl_xor_sync(0xFFFFFFFF, t1, 1));
            t1 = fmaxf(t1, __shfl_xor_sync(0xFFFFFFFF, t1, 2));
            float nm0 = fmaxf(m0, t0), nm1 = fmaxf(m1, t1);
            float sc0 = __expf(m0 - nm0), sc1 = __expf(m1 - nm1);
            m0 = nm0; m1 = nm1;
            l0 *= sc0; l1 *= sc1;
#pragma unroll
            for (int ni = 0; ni < 8; ni++) {
                o[ni][0] *= sc0; o[ni][1] *= sc0;
                o[ni][2] *= sc1; o[ni][3] *= sc1;
            }

            // ---- P = exp(S - m), packed to bf16 hi/lo A-fragments ----
            uint32_t ph[8][2], pl[8][2];
            float rs0 = 0.0f, rs1 = 0.0f;
#pragma unroll
            for (int ni = 0; ni < 8; ni++) {
                float p0 = __expf(s[ni][0] - m0);
                float p1 = __expf(s[ni][1] - m0);
                float p2 = __expf(s[ni][2] - m1);
                float p3 = __expf(s[ni][3] - m1);
                rs0 += p0 + p1;
                rs1 += p2 + p3;
                split2(p0, p1, ph[ni][0], pl[ni][0]);
                split2(p2, p3, ph[ni][1], pl[ni][1]);
            }
            rs0 += __shfl_xor_sync(0xFFFFFFFF, rs0, 1);
            rs0 += __shfl_xor_sync(0xFFFFFFFF, rs0, 2);
            rs1 += __shfl_xor_sync(0xFFFFFFFF, rs1, 1);
            rs1 += __shfl_xor_sync(0xFFFFFFFF, rs1, 2);
            l0 += rs0; l1 += rs1;

            // ---- O += P @ V (3-term); V via ldmatrix.trans ----
#pragma unroll
            for (int kc = 0; kc < 4; kc++) {
                uint32_t ah[4] = { ph[2*kc][0], ph[2*kc][1], ph[2*kc+1][0], ph[2*kc+1][1] };
                uint32_t al[4] = { pl[2*kc][0], pl[2*kc][1], pl[2*kc+1][0], pl[2*kc+1][1] };
#pragma unroll
                for (int ni = 0; ni < 8; ni++) {
                    uint32_t vh[2], vl[2];
                    uint32_t eoff = ((kc * 16 + bl) * AT_LDS + ni * 8) * 2;
                    ldsm_x2t(vh, sb + AT_VHI + eoff);
                    ldsm_x2t(vl, sb + AT_VLO + eoff);
                    mma16816(o[ni], ah, vh);
                    mma16816(o[ni], ah, vl);
                    mma16816(o[ni], al, vh);
                }
            }
        }
        __syncthreads();
    }

    // ---- epilogue ----
    const float inv0 = 1.0f / l0;
    const float inv1 = 1.0f / l1;
    const int b = bh / HH;
    const int h = bh % HH;
    float* dst0 = g_att + ((size_t)b * SS + row0) * DM + h * DK;
    float* dst1 = g_att + ((size_t)b * SS + row0 + 8) * DM + h * DK;
#pragma unroll
    for (int ni = 0; ni < 8; ni++) {
        int col = ni * 8 + qq * 2;
        *(float2*)(dst0 + col) = make_float2(o[ni][0] * inv0, o[ni][1] * inv0);
        *(float2*)(dst1 + col) = make_float2(o[ni][2] * inv1, o[ni][3] * inv1);
    }
}

// ===========================================================================
extern "C" void kernel_launch(void* const* d_in, const int* in_sizes, int n_in,
                              void* d_out, int out_size) {
    const float* x     = (const float*)d_in[0];
    const int*   pos   = (const int*)d_in[1];
    const float* qkv_w = (const float*)d_in[2];
    const float* out_w = (const float*)d_in[3];
    float* out = (float*)d_out;

    cudaFuncSetAttribute(gemm_qkv_kernel, cudaFuncAttributeMaxDynamicSharedMemorySize, GEMM_SMEM);
    cudaFuncSetAttribute(gemm_out_kernel, cudaFuncAttributeMaxDynamicSharedMemorySize, GEMM_SMEM);
    cudaFuncSetAttribute(attn_tc_kernel,  cudaFuncAttributeMaxDynamicSharedMemorySize, ATT_SMEM);

    // 1) QKV projection (mma.sync bf16x3)
    gemm_qkv_kernel<<<dim3(QKVN / 128, BSROWS / 128), 256, GEMM_SMEM>>>(x, qkv_w);

    // 2) RoPE + split/transpose
    {
        int total = BB * SS * HH * (DK / 2);
        rope_split_kernel<<<(total + 255) / 256, 256>>>(pos);
    }

    // 3) Causal flash attention (mma.sync bf16x3)
    attn_tc_kernel<<<dim3(SS / 128, BB * HH), 256, ATT_SMEM>>>();

    // 4) Output projection (mma.sync bf16x3)
    gemm_out_kernel<<<dim3(DM / 128, BSROWS / 128), 256, GEMM_SMEM>>>(out_w, out);
}

// round 7
// speedup vs baseline: 3.0125x; 1.0033x over previous
#include <cuda_runtime.h>
#include <cuda_bf16.h>
#include <math.h>
#include <stdint.h>

#define BB 2
#define SS 2048
#define DM 1024
#define HH 16
#define DK 64
#define BSROWS (BB*SS)      // 4096
#define QKVN (3*DM)         // 3072

// Scratch (allocation-free rule: __device__ globals)
__device__ float g_qkv[(size_t)BSROWS*QKVN];   // [B*S, 3072]
__device__ float g_q[(size_t)BB*HH*SS*DK];     // [B*H, S, 64] (pre-scaled by 1/8)
__device__ float g_k[(size_t)BB*HH*SS*DK];
__device__ float g_v[(size_t)BB*HH*SS*DK];
__device__ float g_att[(size_t)BSROWS*DM];     // [B*S, 1024]

// ===========================================================================
// mma.sync helpers (sm_80+ path — tcgen05 unavailable on this ptxas target)
// ===========================================================================
__device__ __forceinline__ uint32_t smem_u32(const void* p) {
    uint32_t a;
    asm("{ .reg .u64 t; cvta.to.shared.u64 t, %1; cvt.u32.u64 %0, t; }" : "=r"(a) : "l"(p));
    return a;
}
__device__ __forceinline__ void ldsm_x4(uint32_t* r, uint32_t addr) {
    asm volatile("ldmatrix.sync.aligned.m8n8.x4.shared.b16 {%0,%1,%2,%3}, [%4];"
                 : "=r"(r[0]), "=r"(r[1]), "=r"(r[2]), "=r"(r[3]) : "r"(addr));
}
__device__ __forceinline__ void ldsm_x2(uint32_t* r, uint32_t addr) {
    asm volatile("ldmatrix.sync.aligned.m8n8.x2.shared.b16 {%0,%1}, [%2];"
                 : "=r"(r[0]), "=r"(r[1]) : "r"(addr));
}
__device__ __forceinline__ void ldsm_x2t(uint32_t* r, uint32_t addr) {
    asm volatile("ldmatrix.sync.aligned.m8n8.x2.trans.shared.b16 {%0,%1}, [%2];"
                 : "=r"(r[0]), "=r"(r[1]) : "r"(addr));
}
__device__ __forceinline__ void mma16816(float* d, const uint32_t* a, const uint32_t* b) {
    asm volatile("mma.sync.aligned.m16n8k16.row.col.f32.bf16.bf16.f32 "
                 "{%0,%1,%2,%3}, {%4,%5,%6,%7}, {%8,%9}, {%0,%1,%2,%3};"
                 : "+f"(d[0]), "+f"(d[1]), "+f"(d[2]), "+f"(d[3])
                 : "r"(a[0]), "r"(a[1]), "r"(a[2]), "r"(a[3]), "r"(b[0]), "r"(b[1]));
}

__device__ __forceinline__ uint32_t bf2u(__nv_bfloat16 a, __nv_bfloat16 b) {
    __nv_bfloat162 t; t.x = a; t.y = b;
    return *reinterpret_cast<uint32_t*>(&t);
}
// convert a float4 into hi/lo bf16x2 pairs
__device__ __forceinline__ void cvt_hl(float4 v, uint2& hi, uint2& lo) {
    __nv_bfloat16 h0 = __float2bfloat16_rn(v.x);
    __nv_bfloat16 h1 = __float2bfloat16_rn(v.y);
    __nv_bfloat16 h2 = __float2bfloat16_rn(v.z);
    __nv_bfloat16 h3 = __float2bfloat16_rn(v.w);
    __nv_bfloat16 l0 = __float2bfloat16_rn(v.x - __bfloat162float(h0));
    __nv_bfloat16 l1 = __float2bfloat16_rn(v.y - __bfloat162float(h1));
    __nv_bfloat16 l2 = __float2bfloat16_rn(v.z - __bfloat162float(h2));
    __nv_bfloat16 l3 = __float2bfloat16_rn(v.w - __bfloat162float(h3));
    hi = make_uint2(bf2u(h0, h1), bf2u(h2, h3));
    lo = make_uint2(bf2u(l0, l1), bf2u(l2, l3));
}
__device__ __forceinline__ void split2(float a, float b, uint32_t& hi, uint32_t& lo) {
    __nv_bfloat16 h0 = __float2bfloat16_rn(a);
    __nv_bfloat16 h1 = __float2bfloat16_rn(b);
    __nv_bfloat16 l0 = __float2bfloat16_rn(a - __bfloat162float(h0));
    __nv_bfloat16 l1 = __float2bfloat16_rn(b - __bfloat162float(h1));
    hi = bf2u(h0, h1);
    lo = bf2u(l0, l1);
}

// ===========================================================================
// bf16x3 GEMM via mma.sync: C[M,N] = A[M,K] @ W[N,K]^T, fp32 in/out.
// CTA tile 128x128, 8 warps (64x32 each), K-chunk 32, double-buffered smem.
// ===========================================================================
#define KC 32
#define LDAS 40
#define TILE_HL (128 * LDAS * 2)
#define STAGE_B (4 * TILE_HL)
#define GEMM_SMEM (2 * STAGE_B)

#define OFF_AHI 0
#define OFF_ALO TILE_HL
#define OFF_BHI (2*TILE_HL)
#define OFF_BLO (3*TILE_HL)

__device__ __forceinline__
void gemm_tc_body(const float* __restrict__ A, const float* __restrict__ W,
                  float* __restrict__ C, int K, int N) {
    extern __shared__ char smem[];
    const uint32_t sbase = smem_u32(smem);
    const int tid  = threadIdx.x;
    const int wid  = tid >> 5;
    const int lane = tid & 31;
    const int m0 = blockIdx.y * 128;
    const int n0 = blockIdx.x * 128;
    const int wm = wid & 1;
    const int wn = wid >> 1;

    int lrow[4], lkq[4];
#pragma unroll
    for (int it = 0; it < 4; it++) {
        int f = it * 256 + tid;
        lrow[it] = f >> 3;
        lkq[it]  = (f & 7) * 4;
    }

    const int arow = (lane & 7) + ((lane >> 3) & 1) * 8;
    const int acol = (lane >> 4) * 8;
    const int bl   = lane & 15;
    const int brow = bl & 7;
    const int bk   = (bl >> 3) * 8;

    float acc[4][4][4];
#pragma unroll
    for (int mi = 0; mi < 4; mi++)
#pragma unroll
        for (int ni = 0; ni < 4; ni++)
#pragma unroll
            for (int q = 0; q < 4; q++) acc[mi][ni][q] = 0.0f;

    const int nch = K / KC;
    float4 pa[4], pb[4];

#pragma unroll
    for (int it = 0; it < 4; it++) {
        pa[it] = *(const float4*)(A + (size_t)(m0 + lrow[it]) * K + lkq[it]);
        pb[it] = *(const float4*)(W + (size_t)(n0 + lrow[it]) * K + lkq[it]);
    }
    {
        char* stg = smem;
#pragma unroll
        for (int it = 0; it < 4; it++) {
            uint32_t off = (lrow[it] * LDAS + lkq[it]) * 2;
            uint2 hi, lo;
            cvt_hl(pa[it], hi, lo);
            *(uint2*)(stg + OFF_AHI + off) = hi;
            *(uint2*)(stg + OFF_ALO + off) = lo;
            cvt_hl(pb[it], hi, lo);
            *(uint2*)(stg + OFF_BHI + off) = hi;
            *(uint2*)(stg + OFF_BLO + off) = lo;
        }
    }
    __syncthreads();

    for (int c = 0; c < nch; c++) {
        if (c + 1 < nch) {
            const int k0 = (c + 1) * KC;
#pragma unroll
            for (int it = 0; it < 4; it++) {
                pa[it] = *(const float4*)(A + (size_t)(m0 + lrow[it]) * K + k0 + lkq[it]);
                pb[it] = *(const float4*)(W + (size_t)(n0 + lrow[it]) * K + k0 + lkq[it]);
            }
        }

        const uint32_t stg = sbase + (c & 1) * STAGE_B;
#pragma unroll
        for (int ks = 0; ks < 2; ks++) {
            uint32_t ah[4][4], al[4][4], bh[4][2], blr[4][2];
#pragma unroll
            for (int mi = 0; mi < 4; mi++) {
                uint32_t eoff = ((wm * 64 + mi * 16 + arow) * LDAS + ks * 16 + acol) * 2;
                ldsm_x4(ah[mi], stg + OFF_AHI + eoff);
                ldsm_x4(al[mi], stg + OFF_ALO + eoff);
            }
#pragma unroll
            for (int ni = 0; ni < 4; ni++) {
                uint32_t eoff = ((wn * 32 + ni * 8 + brow) * LDAS + ks * 16 + bk) * 2;
                ldsm_x2(bh[ni],  stg + OFF_BHI + eoff);
                ldsm_x2(blr[ni], stg + OFF_BLO + eoff);
            }
#pragma unroll
            for (int mi = 0; mi < 4; mi++)
#pragma unroll
                for (int ni = 0; ni < 4; ni++) {
                    mma16816(acc[mi][ni], ah[mi], bh[ni]);
                    mma16816(acc[mi][ni], ah[mi], blr[ni]);
                    mma16816(acc[mi][ni], al[mi], bh[ni]);
                }
        }
        __syncthreads();

        if (c + 1 < nch) {
            char* stg2 = smem + ((c + 1) & 1) * STAGE_B;
#pragma unroll
            for (int it = 0; it < 4; it++) {
                uint32_t off = (lrow[it] * LDAS + lkq[it]) * 2;
                uint2 hi, lo;
                cvt_hl(pa[it], hi, lo);
                *(uint2*)(stg2 + OFF_AHI + off) = hi;
                *(uint2*)(stg2 + OFF_ALO + off) = lo;
                cvt_hl(pb[it], hi, lo);
                *(uint2*)(stg2 + OFF_BHI + off) = hi;
                *(uint2*)(stg2 + OFF_BLO + off) = lo;
            }
            __syncthreads();
        }
    }

    const int crow = lane >> 2;
    const int ccol = (lane & 3) * 2;
#pragma unroll
    for (int mi = 0; mi < 4; mi++) {
        const size_t r0 = (size_t)(m0 + wm * 64 + mi * 16 + crow);
#pragma unroll
        for (int ni = 0; ni < 4; ni++) {
            const int cc = n0 + wn * 32 + ni * 8 + ccol;
            *(float2*)(C + r0 * N + cc)       = make_float2(acc[mi][ni][0], acc[mi][ni][1]);
            *(float2*)(C + (r0 + 8) * N + cc) = make_float2(acc[mi][ni][2], acc[mi][ni][3]);
        }
    }
}

__global__ __launch_bounds__(256)
void gemm_qkv_kernel(const float* __restrict__ x, const float* __restrict__ qkv_w) {
    gemm_tc_body(x, qkv_w, g_qkv, DM, QKVN);
}
__global__ __launch_bounds__(256)
void gemm_out_kernel(const float* __restrict__ out_w, float* __restrict__ out) {
    gemm_tc_body(g_att, out_w, out, DM, DM);
}

// ===========================================================================
// RoPE + split/transpose: g_qkv [B,S,3,H,DK] -> g_q/g_k/g_v [B*H, S, DK]
// q pre-scaled by 1/sqrt(DK) = 0.125
// ===========================================================================
__global__ void rope_split_kernel(const int* __restrict__ pos) {
    int idx = blockIdx.x * blockDim.x + threadIdx.x;
    const int total = BB * SS * HH * (DK / 2);
    if (idx >= total) return;

    int i = idx & 31;
    int h = (idx >> 5) & (HH - 1);
    int s = (idx >> 9) & (SS - 1);
    int b = idx >> 20;

    int p = pos[b * SS + s];
    float inv_freq = expf(-((float)(2 * i) / (float)DK) * logf(10000.0f));
    float ang = (float)p * inv_freq;
    float c = cosf(ang);
    float sn = sinf(ang);

    const float* base = g_qkv + (size_t)(b * SS + s) * QKVN;
    int col = h * DK + 2 * i;
    float q1 = base[col],          q2 = base[col + 1];
    float k1 = base[DM + col],     k2 = base[DM + col + 1];
    float v1 = base[2 * DM + col], v2 = base[2 * DM + col + 1];

    size_t o = ((size_t)(b * HH + h) * SS + s) * DK + 2 * i;
    const float qs = 0.125f;
    g_q[o]     = (q1 * c - q2 * sn) * qs;
    g_q[o + 1] = (q1 * sn + q2 * c) * qs;
    g_k[o]     = k1 * c - k2 * sn;
    g_k[o + 1] = k1 * sn + k2 * c;
    g_v[o]     = v1;
    g_v[o + 1] = v2;
}

// ===========================================================================
// Tensor-core causal flash attention (bf16x3). CTA = (bh, 128-q-tile),
// 8 warps x m16 row slabs, kv tiles of 64. Smem: K/V/Q hi+lo, stride 72.
// ===========================================================================
#define AT_LDS 72
#define AT_KHI 0
#define AT_KLO 9216
#define AT_VHI 18432
#define AT_VLO 27648
#define AT_QHI 36864
#define AT_QLO 55296
#define ATT_SMEM 73728

__global__ __launch_bounds__(256)
void attn_tc_kernel() {
    extern __shared__ char smem[];
    const uint32_t sb = smem_u32(smem);
    const int tid  = threadIdx.x;
    const int wid  = tid >> 5;
    const int lane = tid & 31;
    const int bh = blockIdx.y;
    const int qt = gridDim.x - 1 - blockIdx.x;   // heavy tiles first
    const int qbase = qt * 128;

    const float* Qb = g_q + (size_t)bh * SS * DK;
    const float* Kb = g_k + (size_t)bh * SS * DK;
    const float* Vb = g_v + (size_t)bh * SS * DK;

    // ---- load Q tile 128x64 -> hi/lo smem ----
#pragma unroll
    for (int it = 0; it < 8; it++) {
        int f = it * 256 + tid;          // 0..2047 float4s
        int row = f >> 4;
        int c4  = (f & 15) * 4;
        float4 v = *(const float4*)(Qb + (size_t)(qbase + row) * DK + c4);
        uint2 hi, lo;
        cvt_hl(v, hi, lo);
        uint32_t off = (row * AT_LDS + c4) * 2;
        *(uint2*)(smem + AT_QHI + off) = hi;
        *(uint2*)(smem + AT_QLO + off) = lo;
    }
    __syncthreads();

    // ---- per-warp Q fragments (rows wid*16..wid*16+15) ----
    const int arow = (lane & 7) + ((lane >> 3) & 1) * 8;
    const int acol = (lane >> 4) * 8;
    uint32_t qh[4][4], ql[4][4];
#pragma unroll
    for (int ks = 0; ks < 4; ks++) {
        uint32_t eoff = ((wid * 16 + arow) * AT_LDS + ks * 16 + acol) * 2;
        ldsm_x4(qh[ks], sb + AT_QHI + eoff);
        ldsm_x4(ql[ks], sb + AT_QLO + eoff);
    }

    float o[8][4];
#pragma unroll
    for (int ni = 0; ni < 8; ni++)
#pragma unroll
        for (int q = 0; q < 4; q++) o[ni][q] = 0.0f;
    float m0 = -INFINITY, m1 = -INFINITY, l0 = 0.0f, l1 = 0.0f;

    const int g  = lane >> 2;
    const int qq = lane & 3;
    const int row0 = qbase + wid * 16 + g;       // row1 = row0 + 8
    const int warp_maxrow = qbase + wid * 16 + 15;

    const int bl = lane & 15;
    const int brow = bl & 7;
    const int bk = (bl >> 3) * 8;

    const int ntiles = (qt + 1) * 2;
    for (int t = 0; t < ntiles; t++) {
        const int kvb = t * 64;

        // ---- cooperative K/V tile load (64x64 fp32 -> bf16 hi/lo) ----
#pragma unroll
        for (int it = 0; it < 4; it++) {
            int f = it * 256 + tid;      // 0..1023 float4s
            int row = f >> 4;
            int c4  = (f & 15) * 4;
            uint32_t off = (row * AT_LDS + c4) * 2;
            uint2 hi, lo;
            float4 kv4 = *(const float4*)(Kb + (size_t)(kvb + row) * DK + c4);
            cvt_hl(kv4, hi, lo);
            *(uint2*)(smem + AT_KHI + off) = hi;
            *(uint2*)(smem + AT_KLO + off) = lo;
            float4 vv4 = *(const float4*)(Vb + (size_t)(kvb + row) * DK + c4);
            cvt_hl(vv4, hi, lo);
            *(uint2*)(smem + AT_VHI + off) = hi;
            *(uint2*)(smem + AT_VLO + off) = lo;
        }
        __syncthreads();

        if (kvb <= warp_maxrow) {
            // ---- S = Q @ K^T (3-term) ----
            float s[8][4];
#pragma unroll
            for (int ni = 0; ni < 8; ni++)
#pragma unroll
                for (int q = 0; q < 4; q++) s[ni][q] = 0.0f;
#pragma unroll
            for (int ks = 0; ks < 4; ks++) {
#pragma unroll
                for (int ni = 0; ni < 8; ni++) {
                    uint32_t kh[2], kl[2];
                    uint32_t eoff = ((ni * 8 + brow) * AT_LDS + ks * 16 + bk) * 2;
                    ldsm_x2(kh, sb + AT_KHI + eoff);
                    ldsm_x2(kl, sb + AT_KLO + eoff);
                    mma16816(s[ni], qh[ks], kh);
                    mma16816(s[ni], qh[ks], kl);
                    mma16816(s[ni], ql[ks], kh);
                }
            }

            // ---- causal mask ----
            if (kvb + 63 > qbase + wid * 16) {
#pragma unroll
                for (int ni = 0; ni < 8; ni++) {
                    int c = kvb + ni * 8 + qq * 2;
                    if (c     > row0)     s[ni][0] = -INFINITY;
                    if (c + 1 > row0)     s[ni][1] = -INFINITY;
                    if (c     > row0 + 8) s[ni][2] = -INFINITY;
                    if (c + 1 > row0 + 8) s[ni][3] = -INFINITY;
                }
            }

            // ---- online softmax ----
            float t0 = -INFINITY, t1 = -INFINITY;
#pragma unroll
            for (int ni = 0; ni < 8; ni++) {
                t0 = fmaxf(t0, fmaxf(s[ni][0], s[ni][1]));
                t1 = fmaxf(t1, fmaxf(s[ni][2], s[ni][3]));
            }
            t0 = fmaxf(t0, __shfl_xor_sync(0xFFFFFFFF, t0, 1));
            t0 = fmaxf(t0, __shfl_xor_sync(0xFFFFFFFF, t0, 2));
            t1 = fmaxf(t1, __shfl_xor_sync(0xFFFFFFFF, t1, 1));
            t1 = fmaxf(t1, __shfl_xor_sync(0xFFFFFFFF, t1, 2));
            float nm0 = fmaxf(m0, t0), nm1 = fmaxf(m1, t1);
            float sc0 = __expf(m0 - nm0), sc1 = __expf(m1 - nm1);
            m0 = nm0; m1 = nm1;
            l0 *= sc0; l1 *= sc1;
#pragma unroll
            for (int ni = 0; ni < 8; ni++) {
                o[ni][0] *= sc0; o[ni][1] *= sc0;
                o[ni][2] *= sc1; o[ni][3] *= sc1;
            }

            // ---- P = exp(S - m), packed to bf16 hi/lo A-fragments ----
            uint32_t ph[8][2], pl[8][2];
            float rs0 = 0.0f, rs1 = 0.0f;
#pragma unroll
            for (int ni = 0; ni < 8; ni++) {
                float p0 = __expf(s[ni][0] - m0);
                float p1 = __expf(s[ni][1] - m0);
                float p2 = __expf(s[ni][2] - m1);
                float p3 = __expf(s[ni][3] - m1);
                rs0 += p0 + p1;
                rs1 += p2 + p3;
                split2(p0, p1, ph[ni][0], pl[ni][0]);
                split2(p2, p3, ph[ni][1], pl[ni][1]);
            }
            rs0 += __shfl_xor_sync(0xFFFFFFFF, rs0, 1);
            rs0 += __shfl_xor_sync(0xFFFFFFFF, rs0, 2);
            rs1 += __shfl_xor_sync(0xFFFFFFFF, rs1, 1);
            rs1 += __shfl_xor_sync(0xFFFFFFFF, rs1, 2);
            l0 += rs0; l1 += rs1;

            // ---- O += P @ V (3-term); V via ldmatrix.trans ----
#pragma unroll
            for (int kc = 0; kc < 4; kc++) {
                uint32_t ah[4] = { ph[2*kc][0], ph[2*kc][1], ph[2*kc+1][0], ph[2*kc+1][1] };
                uint32_t al[4] = { pl[2*kc][0], pl[2*kc][1], pl[2*kc+1][0], pl[2*kc+1][1] };
#pragma unroll
                for (int ni = 0; ni < 8; ni++) {
                    uint32_t vh[2], vl[2];
                    uint32_t eoff = ((kc * 16 + bl) * AT_LDS + ni * 8) * 2;
                    ldsm_x2t(vh, sb + AT_VHI + eoff);
                    ldsm_x2t(vl, sb + AT_VLO + eoff);
                    mma16816(o[ni], ah, vh);
                    mma16816(o[ni], ah, vl);
                    mma16816(o[ni], al, vh);
                }
            }
        }
        __syncthreads();
    }

    // ---- epilogue ----
    const float inv0 = 1.0f / l0;
    const float inv1 = 1.0f / l1;
    const int b = bh / HH;
    const int h = bh % HH;
    float* dst0 = g_att + ((size_t)b * SS + row0) * DM + h * DK;
    float* dst1 = g_att + ((size_t)b * SS + row0 + 8) * DM + h * DK;
#pragma unroll
    for (int ni = 0; ni < 8; ni++) {
        int col = ni * 8 + qq * 2;
        *(float2*)(dst0 + col) = make_float2(o[ni][0] * inv0, o[ni][1] * inv0);
        *(float2*)(dst1 + col) = make_float2(o[ni][2] * inv1, o[ni][3] * inv1);
    }
}

// ===========================================================================
extern "C" void kernel_launch(void* const* d_in, const int* in_sizes, int n_in,
                              void* d_out, int out_size) {
    const float* x     = (const float*)d_in[0];
    const int*   pos   = (const int*)d_in[1];
    const float* qkv_w = (const float*)d_in[2];
    const float* out_w = (const float*)d_in[3];
    float* out = (float*)d_out;

    cudaFuncSetAttribute(gemm_qkv_kernel, cudaFuncAttributeMaxDynamicSharedMemorySize, GEMM_SMEM);
    cudaFuncSetAttribute(gemm_out_kernel, cudaFuncAttributeMaxDynamicSharedMemorySize, GEMM_SMEM);
    cudaFuncSetAttribute(attn_tc_kernel,  cudaFuncAttributeMaxDynamicSharedMemorySize, ATT_SMEM);

    // 1) QKV projection (mma.sync bf16x3)
    gemm_qkv_kernel<<<dim3(QKVN / 128, BSROWS / 128), 256, GEMM_SMEM>>>(x, qkv_w);

    // 2) RoPE + split/transpose
    {
        int total = BB * SS * HH * (DK / 2);
        rope_split_kernel<<<(total + 255) / 256, 256>>>(pos);
    }

    // 3) Causal flash attention (mma.sync bf16x3)
    attn_tc_kernel<<<dim3(SS / 128, BB * HH), 256, ATT_SMEM>>>();

    // 4) Output projection (mma.sync bf16x3)
    gemm_out_kernel<<<dim3(DM / 128, BSROWS / 128), 256, GEMM_SMEM>>>(out_w, out);
}

// round 8
// speedup vs baseline: 3.2725x; 1.0863x over previous
#include <cuda_runtime.h>
#include <cuda_bf16.h>
#include <math.h>
#include <stdint.h>

#define BB 2
#define SS 2048
#define DM 1024
#define HH 16
#define DK 64
#define BSROWS (BB*SS)      // 4096
#define QKVN (3*DM)         // 3072

// ===========================================================================
// Scratch (allocation-free rule: __device__ globals). Everything bf16 hi/lo.
// ===========================================================================
__device__ __align__(16) __nv_bfloat16 x_hi[(size_t)BSROWS*DM];
__device__ __align__(16) __nv_bfloat16 x_lo[(size_t)BSROWS*DM];
__device__ __align__(16) __nv_bfloat16 wq_hi[(size_t)QKVN*DM];
__device__ __align__(16) __nv_bfloat16 wq_lo[(size_t)QKVN*DM];
__device__ __align__(16) __nv_bfloat16 wo_hi[(size_t)DM*DM];
__device__ __align__(16) __nv_bfloat16 wo_lo[(size_t)DM*DM];
__device__ __align__(16) __nv_bfloat16 q_hi[(size_t)BB*HH*SS*DK];
__device__ __align__(16) __nv_bfloat16 q_lo[(size_t)BB*HH*SS*DK];
__device__ __align__(16) __nv_bfloat16 k_hi[(size_t)BB*HH*SS*DK];
__device__ __align__(16) __nv_bfloat16 k_lo[(size_t)BB*HH*SS*DK];
__device__ __align__(16) __nv_bfloat16 v_hi[(size_t)BB*HH*SS*DK];
__device__ __align__(16) __nv_bfloat16 v_lo[(size_t)BB*HH*SS*DK];
__device__ __align__(16) __nv_bfloat16 att_hi[(size_t)BSROWS*DM];
__device__ __align__(16) __nv_bfloat16 att_lo[(size_t)BSROWS*DM];

// ===========================================================================
// PTX helpers
// ===========================================================================
__device__ __forceinline__ uint32_t smem_u32(const void* p) {
    uint32_t a;
    asm("{ .reg .u64 t; cvta.to.shared.u64 t, %1; cvt.u32.u64 %0, t; }" : "=r"(a) : "l"(p));
    return a;
}
__device__ __forceinline__ void ldsm_x4(uint32_t* r, uint32_t addr) {
    asm volatile("ldmatrix.sync.aligned.m8n8.x4.shared.b16 {%0,%1,%2,%3}, [%4];"
                 : "=r"(r[0]), "=r"(r[1]), "=r"(r[2]), "=r"(r[3]) : "r"(addr));
}
__device__ __forceinline__ void ldsm_x2(uint32_t* r, uint32_t addr) {
    asm volatile("ldmatrix.sync.aligned.m8n8.x2.shared.b16 {%0,%1}, [%2];"
                 : "=r"(r[0]), "=r"(r[1]) : "r"(addr));
}
__device__ __forceinline__ void ldsm_x2t(uint32_t* r, uint32_t addr) {
    asm volatile("ldmatrix.sync.aligned.m8n8.x2.trans.shared.b16 {%0,%1}, [%2];"
                 : "=r"(r[0]), "=r"(r[1]) : "r"(addr));
}
__device__ __forceinline__ void mma16816(float* d, const uint32_t* a, const uint32_t* b) {
    asm volatile("mma.sync.aligned.m16n8k16.row.col.f32.bf16.bf16.f32 "
                 "{%0,%1,%2,%3}, {%4,%5,%6,%7}, {%8,%9}, {%0,%1,%2,%3};"
                 : "+f"(d[0]), "+f"(d[1]), "+f"(d[2]), "+f"(d[3])
                 : "r"(a[0]), "r"(a[1]), "r"(a[2]), "r"(a[3]), "r"(b[0]), "r"(b[1]));
}
__device__ __forceinline__ void cp16(uint32_t saddr, const void* g) {
    asm volatile("cp.async.cg.shared.global [%0], [%1], 16;" :: "r"(saddr), "l"(g));
}
#define CP_COMMIT() asm volatile("cp.async.commit_group;" ::: "memory")
#define CP_WAIT1()  asm volatile("cp.async.wait_group 1;" ::: "memory")
#define CP_WAIT0()  asm volatile("cp.async.wait_group 0;" ::: "memory")

__device__ __forceinline__ uint32_t bf2u(__nv_bfloat16 a, __nv_bfloat16 b) {
    __nv_bfloat162 t; t.x = a; t.y = b;
    return *reinterpret_cast<uint32_t*>(&t);
}
__device__ __forceinline__ void cvt_hl(float4 v, uint2& hi, uint2& lo) {
    __nv_bfloat16 h0 = __float2bfloat16_rn(v.x);
    __nv_bfloat16 h1 = __float2bfloat16_rn(v.y);
    __nv_bfloat16 h2 = __float2bfloat16_rn(v.z);
    __nv_bfloat16 h3 = __float2bfloat16_rn(v.w);
    __nv_bfloat16 l0 = __float2bfloat16_rn(v.x - __bfloat162float(h0));
    __nv_bfloat16 l1 = __float2bfloat16_rn(v.y - __bfloat162float(h1));
    __nv_bfloat16 l2 = __float2bfloat16_rn(v.z - __bfloat162float(h2));
    __nv_bfloat16 l3 = __float2bfloat16_rn(v.w - __bfloat162float(h3));
    hi = make_uint2(bf2u(h0, h1), bf2u(h2, h3));
    lo = make_uint2(bf2u(l0, l1), bf2u(l2, l3));
}
__device__ __forceinline__ void split2(float a, float b, uint32_t& hi, uint32_t& lo) {
    __nv_bfloat16 h0 = __float2bfloat16_rn(a);
    __nv_bfloat16 h1 = __float2bfloat16_rn(b);
    __nv_bfloat16 l0 = __float2bfloat16_rn(a - __bfloat162float(h0));
    __nv_bfloat16 l1 = __float2bfloat16_rn(b - __bfloat162float(h1));
    hi = bf2u(h0, h1);
    lo = bf2u(l0, l1);
}

// ===========================================================================
// Convert: split x / qkv_w / out_w fp32 -> bf16 hi/lo
// ===========================================================================
#define N4_X  (BSROWS*DM/4)
#define N4_WQ (QKVN*DM/4)
#define N4_WO (DM*DM/4)
#define N4_TOTAL (N4_X + N4_WQ + N4_WO)

__global__ __launch_bounds__(256)
void cvt_split_kernel(const float* __restrict__ x, const float* __restrict__ wq,
                      const float* __restrict__ wo) {
    int i = blockIdx.x * blockDim.x + threadIdx.x;
    const float4* s; uint2 *dh, *dl; int j;
    if (i < N4_X)                  { j = i;                 s = (const float4*)x;  dh = (uint2*)x_hi;  dl = (uint2*)x_lo; }
    else if (i < N4_X + N4_WQ)     { j = i - N4_X;          s = (const float4*)wq; dh = (uint2*)wq_hi; dl = (uint2*)wq_lo; }
    else                           { j = i - N4_X - N4_WQ;  s = (const float4*)wo; dh = (uint2*)wo_hi; dl = (uint2*)wo_lo; }
    float4 v = s[j];
    uint2 h, l;
    cvt_hl(v, h, l);
    dh[j] = h; dl[j] = l;
}

// ===========================================================================
// bf16x3 GEMM via mma.sync + cp.async. C[M,N] = A[M,1024] @ B[N,1024]^T.
// CTA tile 128x128, 8 warps (64x32), K-chunk 32, 2-stage cp.async pipeline.
// MODE 0: store fp32 C. MODE 1: fused RoPE epilogue -> q/k/v hi/lo.
// ===========================================================================
#define KC 32
#define LDAS 40
#define TILE_HL (128 * LDAS * 2)        // 10240 B
#define STAGE_B (4 * TILE_HL)           // 40960 B
#define GEMM_SMEM (2 * STAGE_B)         // 81920 B
#define OFF_AHI 0
#define OFF_ALO TILE_HL
#define OFF_BHI (2*TILE_HL)
#define OFF_BLO (3*TILE_HL)
#define KLOG 0.28782313662f             // 2/64 * ln(10000)

template<int MODE>
__global__ __launch_bounds__(256, 2)
void gemm_bf16x3_kernel(const __nv_bfloat16* __restrict__ Ahi, const __nv_bfloat16* __restrict__ Alo,
                        const __nv_bfloat16* __restrict__ Bhi, const __nv_bfloat16* __restrict__ Blo,
                        float* __restrict__ C, const int* __restrict__ pos, int N) {
    extern __shared__ char smem[];
    const uint32_t sbase = smem_u32(smem);
    const int tid  = threadIdx.x;
    const int wid  = tid >> 5;
    const int lane = tid & 31;
    const int m0 = blockIdx.y * 128;
    const int n0 = blockIdx.x * 128;
    const int wm = wid & 1;
    const int wn = wid >> 1;

    const uint4* Ah4 = (const uint4*)Ahi;
    const uint4* Al4 = (const uint4*)Alo;
    const uint4* Bh4 = (const uint4*)Bhi;
    const uint4* Bl4 = (const uint4*)Blo;

    // chunk issue: 128x32 bf16 per tile, 2 uint4 per thread per array
    int lrow[2], lch[2];
#pragma unroll
    for (int it = 0; it < 2; it++) {
        int f = it * 256 + tid;
        lrow[it] = f >> 2;
        lch[it]  = (f & 3) * 8;
    }
    auto issue = [&](int c, int s) {
        const int k0 = c * KC;
#pragma unroll
        for (int it = 0; it < 2; it++) {
            size_t gi = ((size_t)(m0 + lrow[it]) * DM + k0 + lch[it]) >> 3;
            size_t gj = ((size_t)(n0 + lrow[it]) * DM + k0 + lch[it]) >> 3;
            uint32_t so = sbase + s * STAGE_B + (uint32_t)(lrow[it] * LDAS + lch[it]) * 2;
            cp16(so + OFF_AHI, Ah4 + gi);
            cp16(so + OFF_ALO, Al4 + gi);
            cp16(so + OFF_BHI, Bh4 + gj);
            cp16(so + OFF_BLO, Bl4 + gj);
        }
    };

    const int arow = (lane & 7) + ((lane >> 3) & 1) * 8;
    const int acol = (lane >> 4) * 8;
    const int bl   = lane & 15;
    const int brow = bl & 7;
    const int bk   = (bl >> 3) * 8;

    float acc[4][4][4];
#pragma unroll
    for (int mi = 0; mi < 4; mi++)
#pragma unroll
        for (int ni = 0; ni < 4; ni++)
#pragma unroll
            for (int q = 0; q < 4; q++) acc[mi][ni][q] = 0.0f;

    const int nch = DM / KC;   // 32
    issue(0, 0); CP_COMMIT();
    issue(1, 1); CP_COMMIT();

    for (int c = 0; c < nch; c++) {
        if (c + 1 < nch) CP_WAIT1(); else CP_WAIT0();
        __syncthreads();

        const uint32_t stg = sbase + (c & 1) * STAGE_B;
#pragma unroll
        for (int ks = 0; ks < 2; ks++) {
            uint32_t ah[4][4], al[4][4];
#pragma unroll
            for (int mi = 0; mi < 4; mi++) {
                uint32_t eoff = ((wm * 64 + mi * 16 + arow) * LDAS + ks * 16 + acol) * 2;
                ldsm_x4(ah[mi], stg + OFF_AHI + eoff);
                ldsm_x4(al[mi], stg + OFF_ALO + eoff);
            }
#pragma unroll
            for (int ni = 0; ni < 4; ni++) {
                uint32_t bhf[2], blf[2];
                uint32_t eoff = ((wn * 32 + ni * 8 + brow) * LDAS + ks * 16 + bk) * 2;
                ldsm_x2(bhf, stg + OFF_BHI + eoff);
                ldsm_x2(blf, stg + OFF_BLO + eoff);
#pragma unroll
                for (int mi = 0; mi < 4; mi++) {
                    mma16816(acc[mi][ni], ah[mi], bhf);
                    mma16816(acc[mi][ni], ah[mi], blf);
                    mma16816(acc[mi][ni], al[mi], bhf);
                }
            }
        }
        __syncthreads();
        if (c + 2 < nch) { issue(c + 2, c & 1); CP_COMMIT(); }
    }

    const int crow = lane >> 2;
    const int ccol = (lane & 3) * 2;

    if (MODE == 0) {
#pragma unroll
        for (int mi = 0; mi < 4; mi++) {
            const size_t r0 = (size_t)(m0 + wm * 64 + mi * 16 + crow);
#pragma unroll
            for (int ni = 0; ni < 4; ni++) {
                const int cc = n0 + wn * 32 + ni * 8 + ccol;
                *(float2*)(C + r0 * N + cc)       = make_float2(acc[mi][ni][0], acc[mi][ni][1]);
                *(float2*)(C + (r0 + 8) * N + cc) = make_float2(acc[mi][ni][2], acc[mi][ni][3]);
            }
        }
    } else {
        // fused RoPE: n0 selects section (0=q rope*0.125, 1=k rope, 2=v copy)
        const int sec  = n0 >> 10;
        const int nmod = n0 & 1023;
        int hh_[4], ii_[4];
        float ifr_[4];
#pragma unroll
        for (int ni = 0; ni < 4; ni++) {
            int colmod = nmod + wn * 32 + ni * 8 + ccol;
            hh_[ni] = colmod >> 6;
            ii_[ni] = (colmod & 63) >> 1;
            ifr_[ni] = (sec < 2) ? expf(-(float)ii_[ni] * KLOG) : 0.0f;
        }
        uint32_t* ghi = (sec == 0) ? (uint32_t*)q_hi : (sec == 1) ? (uint32_t*)k_hi : (uint32_t*)v_hi;
        uint32_t* glo = (sec == 0) ? (uint32_t*)q_lo : (sec == 1) ? (uint32_t*)k_lo : (uint32_t*)v_lo;
#pragma unroll
        for (int mi = 0; mi < 4; mi++) {
            const int rbase = m0 + wm * 64 + mi * 16 + crow;
#pragma unroll
            for (int half = 0; half < 2; half++) {
                const int r = rbase + half * 8;
                const int p = pos[r];
                const int b = r >> 11;
                const int s = r & 2047;
#pragma unroll
                for (int ni = 0; ni < 4; ni++) {
                    float v0 = acc[mi][ni][half * 2];
                    float v1 = acc[mi][ni][half * 2 + 1];
                    float o0, o1;
                    if (sec < 2) {
                        float ang = (float)p * ifr_[ni];
                        float cs = cosf(ang), sn = sinf(ang);
                        o0 = v0 * cs - v1 * sn;
                        o1 = v0 * sn + v1 * cs;
                        if (sec == 0) { o0 *= 0.125f; o1 *= 0.125f; }
                    } else { o0 = v0; o1 = v1; }
                    uint32_t hi, lo;
                    split2(o0, o1, hi, lo);
                    size_t idx = ((size_t)(b * HH + hh_[ni]) * SS + s) * 32 + ii_[ni];
                    ghi[idx] = hi;
                    glo[idx] = lo;
                }
            }
        }
    }
}

// ===========================================================================
// Tensor-core causal flash attention (bf16x3), pre-split q/k/v inputs.
// CTA = (bh, 128-q-tile), 8 warps x m16 slabs, kv tiles of 64,
// double-buffered cp.async K/V. Output written pre-split to att_hi/att_lo.
// ===========================================================================
#define AT_LDS 72
#define AT_STG 36864                    // one KV stage: Khi,Klo,Vhi,Vlo @ 9216
#define AT_QHI 73728
#define AT_QLO 92160
#define ATT_SMEM 110592

__global__ __launch_bounds__(256)
void attn_tc_kernel() {
    extern __shared__ char smem[];
    const uint32_t sb = smem_u32(smem);
    const int tid  = threadIdx.x;
    const int wid  = tid >> 5;
    const int lane = tid & 31;
    const int bh = blockIdx.y;
    const int qt = gridDim.x - 1 - blockIdx.x;   // heavy tiles first
    const int qbase = qt * 128;

    const uint4* qh4 = (const uint4*)q_hi + (size_t)bh * SS * 8;
    const uint4* ql4 = (const uint4*)q_lo + (size_t)bh * SS * 8;
    const uint4* kh4 = (const uint4*)k_hi + (size_t)bh * SS * 8;
    const uint4* kl4 = (const uint4*)k_lo + (size_t)bh * SS * 8;
    const uint4* vh4 = (const uint4*)v_hi + (size_t)bh * SS * 8;
    const uint4* vl4 = (const uint4*)v_lo + (size_t)bh * SS * 8;

    // ---- load Q tile 128x64 hi/lo (4 uint4/thread/array) ----
#pragma unroll
    for (int it = 0; it < 4; it++) {
        int f = it * 256 + tid;
        int row = f >> 3;
        int ch  = f & 7;
        uint32_t so = (uint32_t)(row * AT_LDS + ch * 8) * 2;
        *(uint4*)(smem + AT_QHI + so) = qh4[(size_t)(qbase + row) * 8 + ch];
        *(uint4*)(smem + AT_QLO + so) = ql4[(size_t)(qbase + row) * 8 + ch];
    }
    __syncthreads();

    const int arow = (lane & 7) + ((lane >> 3) & 1) * 8;
    const int acol = (lane >> 4) * 8;
    uint32_t qh[4][4], ql[4][4];
#pragma unroll
    for (int ks = 0; ks < 4; ks++) {
        uint32_t eoff = ((wid * 16 + arow) * AT_LDS + ks * 16 + acol) * 2;
        ldsm_x4(qh[ks], sb + AT_QHI + eoff);
        ldsm_x4(ql[ks], sb + AT_QLO + eoff);
    }

    float o[8][4];
#pragma unroll
    for (int ni = 0; ni < 8; ni++)
#pragma unroll
        for (int q = 0; q < 4; q++) o[ni][q] = 0.0f;
    float m0 = -INFINITY, m1 = -INFINITY, l0 = 0.0f, l1 = 0.0f;

    const int g  = lane >> 2;
    const int qq = lane & 3;
    const int row0 = qbase + wid * 16 + g;
    const int warp_maxrow = qbase + wid * 16 + 15;

    const int bl = lane & 15;
    const int brow = bl & 7;
    const int bk = (bl >> 3) * 8;

    // KV tile async loader: 2 uint4/thread/array
    auto kv_issue = [&](int t, int s) {
        const int kvb = t * 64;
#pragma unroll
        for (int it = 0; it < 2; it++) {
            int f = it * 256 + tid;
            int row = f >> 3;
            int ch  = f & 7;
            uint32_t so = sb + s * AT_STG + (uint32_t)(row * AT_LDS + ch * 8) * 2;
            size_t gi = (size_t)(kvb + row) * 8 + ch;
            cp16(so,         kh4 + gi);
            cp16(so +  9216, kl4 + gi);
            cp16(so + 18432, vh4 + gi);
            cp16(so + 27648, vl4 + gi);
        }
    };

    const int ntiles = (qt + 1) * 2;
    kv_issue(0, 0); CP_COMMIT();

    for (int t = 0; t < ntiles; t++) {
        if (t + 1 < ntiles) { kv_issue(t + 1, (t + 1) & 1); CP_COMMIT(); CP_WAIT1(); }
        else CP_WAIT0();
        __syncthreads();

        const int kvb = t * 64;
        const uint32_t stg = sb + (t & 1) * AT_STG;

        if (kvb <= warp_maxrow) {
            // ---- S = Q @ K^T (3-term) ----
            float s[8][4];
#pragma unroll
            for (int ni = 0; ni < 8; ni++)
#pragma unroll
                for (int q = 0; q < 4; q++) s[ni][q] = 0.0f;
#pragma unroll
            for (int ks = 0; ks < 4; ks++) {
#pragma unroll
                for (int ni = 0; ni < 8; ni++) {
                    uint32_t khf[2], klf[2];
                    uint32_t eoff = ((ni * 8 + brow) * AT_LDS + ks * 16 + bk) * 2;
                    ldsm_x2(khf, stg + eoff);
                    ldsm_x2(klf, stg + 9216 + eoff);
                    mma16816(s[ni], qh[ks], khf);
                    mma16816(s[ni], qh[ks], klf);
                    mma16816(s[ni], ql[ks], khf);
                }
            }

            // ---- causal mask ----
            if (kvb + 63 > qbase + wid * 16) {
#pragma unroll
                for (int ni = 0; ni < 8; ni++) {
                    int c = kvb + ni * 8 + qq * 2;
                    if (c     > row0)     s[ni][0] = -INFINITY;
                    if (c + 1 > row0)     s[ni][1] = -INFINITY;
                    if (c     > row0 + 8) s[ni][2] = -INFINITY;
                    if (c + 1 > row0 + 8) s[ni][3] = -INFINITY;
                }
            }

            // ---- online softmax ----
            float t0 = -INFINITY, t1 = -INFINITY;
#pragma unroll
            for (int ni = 0; ni < 8; ni++) {
                t0 = fmaxf(t0, fmaxf(s[ni][0], s[ni][1]));
                t1 = fmaxf(t1, fmaxf(s[ni][2], s[ni][3]));
            }
            t0 = fmaxf(t0, __shfl_xor_sync(0xFFFFFFFF, t0, 1));
            t0 = fmaxf(t0, __shfl_xor_sync(0xFFFFFFFF, t0, 2));
            t1 = fmaxf(t1, __shfl_xor_sync(0xFFFFFFFF, t1, 1));
            t1 = fmaxf(t1, __shfl_xor_sync(0xFFFFFFFF, t1, 2));
            float nm0 = fmaxf(m0, t0), nm1 = fmaxf(m1, t1);
            float sc0 = __expf(m0 - nm0), sc1 = __expf(m1 - nm1);
            m0 = nm0; m1 = nm1;
            l0 *= sc0; l1 *= sc1;
#pragma unroll
            for (int ni = 0; ni < 8; ni++) {
                o[ni][0] *= sc0; o[ni][1] *= sc0;
                o[ni][2] *= sc1; o[ni][3] *= sc1;
            }

            // ---- P = exp(S - m) -> bf16 hi/lo A-fragments ----
            uint32_t ph[8][2], pl[8][2];
            float rs0 = 0.0f, rs1 = 0.0f;
#pragma unroll
            for (int ni = 0; ni < 8; ni++) {
                float p0 = __expf(s[ni][0] - m0);
                float p1 = __expf(s[ni][1] - m0);
                float p2 = __expf(s[ni][2] - m1);
                float p3 = __expf(s[ni][3] - m1);
                rs0 += p0 + p1;
                rs1 += p2 + p3;
                split2(p0, p1, ph[ni][0], pl[ni][0]);
                split2(p2, p3, ph[ni][1], pl[ni][1]);
            }
            rs0 += __shfl_xor_sync(0xFFFFFFFF, rs0, 1);
            rs0 += __shfl_xor_sync(0xFFFFFFFF, rs0, 2);
            rs1 += __shfl_xor_sync(0xFFFFFFFF, rs1, 1);
            rs1 += __shfl_xor_sync(0xFFFFFFFF, rs1, 2);
            l0 += rs0; l1 += rs1;

            // ---- O += P @ V (3-term); V via ldmatrix.trans ----
#pragma unroll
            for (int kc = 0; kc < 4; kc++) {
                uint32_t ah[4] = { ph[2*kc][0], ph[2*kc][1], ph[2*kc+1][0], ph[2*kc+1][1] };
                uint32_t al[4] = { pl[2*kc][0], pl[2*kc][1], pl[2*kc+1][0], pl[2*kc+1][1] };
#pragma unroll
                for (int ni = 0; ni < 8; ni++) {
                    uint32_t vhf[2], vlf[2];
                    uint32_t eoff = ((kc * 16 + bl) * AT_LDS + ni * 8) * 2;
                    ldsm_x2t(vhf, stg + 18432 + eoff);
                    ldsm_x2t(vlf, stg + 27648 + eoff);
                    mma16816(o[ni], ah, vhf);
                    mma16816(o[ni], ah, vlf);
                    mma16816(o[ni], al, vhf);
                }
            }
        }
        __syncthreads();
    }

    // ---- epilogue: normalize + split -> att_hi/att_lo ----
    const float inv0 = 1.0f / l0;
    const float inv1 = 1.0f / l1;
    const int b = bh / HH;
    const int h = bh % HH;
    uint32_t* ahi32 = (uint32_t*)att_hi;
    uint32_t* alo32 = (uint32_t*)att_lo;
    const size_t base0 = ((size_t)b * SS + row0) * 512 + h * 32;
    const size_t base1 = ((size_t)b * SS + row0 + 8) * 512 + h * 32;
#pragma unroll
    for (int ni = 0; ni < 8; ni++) {
        uint32_t hi, lo;
        split2(o[ni][0] * inv0, o[ni][1] * inv0, hi, lo);
        ahi32[base0 + ni * 4 + qq] = hi;
        alo32[base0 + ni * 4 + qq] = lo;
        split2(o[ni][2] * inv1, o[ni][3] * inv1, hi, lo);
        ahi32[base1 + ni * 4 + qq] = hi;
        alo32[base1 + ni * 4 + qq] = lo;
    }
}

// ===========================================================================
extern "C" void kernel_launch(void* const* d_in, const int* in_sizes, int n_in,
                              void* d_out, int out_size) {
    const float* x     = (const float*)d_in[0];
    const int*   pos   = (const int*)d_in[1];
    const float* qkv_w = (const float*)d_in[2];
    const float* out_w = (const float*)d_in[3];
    float* out = (float*)d_out;

    __nv_bfloat16 *p_xhi, *p_xlo, *p_wqhi, *p_wqlo, *p_wohi, *p_wolo, *p_ahi, *p_alo;
    cudaGetSymbolAddress((void**)&p_xhi,  x_hi);
    cudaGetSymbolAddress((void**)&p_xlo,  x_lo);
    cudaGetSymbolAddress((void**)&p_wqhi, wq_hi);
    cudaGetSymbolAddress((void**)&p_wqlo, wq_lo);
    cudaGetSymbolAddress((void**)&p_wohi, wo_hi);
    cudaGetSymbolAddress((void**)&p_wolo, wo_lo);
    cudaGetSymbolAddress((void**)&p_ahi,  att_hi);
    cudaGetSymbolAddress((void**)&p_alo,  att_lo);

    cudaFuncSetAttribute(gemm_bf16x3_kernel<0>, cudaFuncAttributeMaxDynamicSharedMemorySize, GEMM_SMEM);
    cudaFuncSetAttribute(gemm_bf16x3_kernel<1>, cudaFuncAttributeMaxDynamicSharedMemorySize, GEMM_SMEM);
    cudaFuncSetAttribute(attn_tc_kernel,        cudaFuncAttributeMaxDynamicSharedMemorySize, ATT_SMEM);

    // 0) fp32 -> bf16 hi/lo for x, qkv_w, out_w
    cvt_split_kernel<<<N4_TOTAL / 256, 256>>>(x, qkv_w, out_w);

    // 1) QKV projection + fused RoPE -> q/k/v hi/lo
    gemm_bf16x3_kernel<1><<<dim3(QKVN / 128, BSROWS / 128), 256, GEMM_SMEM>>>(
        p_xhi, p_xlo, p_wqhi, p_wqlo, nullptr, pos, QKVN);

    // 2) Causal flash attention -> att hi/lo
    attn_tc_kernel<<<dim3(SS / 128, BB * HH), 256, ATT_SMEM>>>();

    // 3) Output projection -> fp32 out
    gemm_bf16x3_kernel<0><<<dim3(DM / 128, BSROWS / 128), 256, GEMM_SMEM>>>(
        p_ahi, p_alo, p_wohi, p_wolo, out, nullptr, DM);
}

// round 9
// speedup vs baseline: 3.2840x; 1.0035x over previous
#include <cuda_runtime.h>
#include <cuda_bf16.h>
#include <math.h>
#include <stdint.h>

#define BB 2
#define SS 2048
#define DM 1024
#define HH 16
#define DK 64
#define BSROWS (BB*SS)      // 4096
#define QKVN (3*DM)         // 3072

// ===========================================================================
// Scratch (allocation-free rule: __device__ globals). Everything bf16 hi/lo.
// ===========================================================================
__device__ __align__(16) __nv_bfloat16 x_hi[(size_t)BSROWS*DM];
__device__ __align__(16) __nv_bfloat16 x_lo[(size_t)BSROWS*DM];
__device__ __align__(16) __nv_bfloat16 wq_hi[(size_t)QKVN*DM];
__device__ __align__(16) __nv_bfloat16 wq_lo[(size_t)QKVN*DM];
__device__ __align__(16) __nv_bfloat16 wo_hi[(size_t)DM*DM];
__device__ __align__(16) __nv_bfloat16 wo_lo[(size_t)DM*DM];
__device__ __align__(16) __nv_bfloat16 q_hi[(size_t)BB*HH*SS*DK];
__device__ __align__(16) __nv_bfloat16 q_lo[(size_t)BB*HH*SS*DK];
__device__ __align__(16) __nv_bfloat16 k_hi[(size_t)BB*HH*SS*DK];
__device__ __align__(16) __nv_bfloat16 k_lo[(size_t)BB*HH*SS*DK];
__device__ __align__(16) __nv_bfloat16 v_hi[(size_t)BB*HH*SS*DK];
__device__ __align__(16) __nv_bfloat16 v_lo[(size_t)BB*HH*SS*DK];
__device__ __align__(16) __nv_bfloat16 att_hi[(size_t)BSROWS*DM];
__device__ __align__(16) __nv_bfloat16 att_lo[(size_t)BSROWS*DM];

// ===========================================================================
// PTX helpers
// ===========================================================================
__device__ __forceinline__ uint32_t smem_u32(const void* p) {
    uint32_t a;
    asm("{ .reg .u64 t; cvta.to.shared.u64 t, %1; cvt.u32.u64 %0, t; }" : "=r"(a) : "l"(p));
    return a;
}
__device__ __forceinline__ void ldsm_x4(uint32_t* r, uint32_t addr) {
    asm volatile("ldmatrix.sync.aligned.m8n8.x4.shared.b16 {%0,%1,%2,%3}, [%4];"
                 : "=r"(r[0]), "=r"(r[1]), "=r"(r[2]), "=r"(r[3]) : "r"(addr));
}
__device__ __forceinline__ void ldsm_x2(uint32_t* r, uint32_t addr) {
    asm volatile("ldmatrix.sync.aligned.m8n8.x2.shared.b16 {%0,%1}, [%2];"
                 : "=r"(r[0]), "=r"(r[1]) : "r"(addr));
}
__device__ __forceinline__ void ldsm_x2t(uint32_t* r, uint32_t addr) {
    asm volatile("ldmatrix.sync.aligned.m8n8.x2.trans.shared.b16 {%0,%1}, [%2];"
                 : "=r"(r[0]), "=r"(r[1]) : "r"(addr));
}
__device__ __forceinline__ void mma16816(float* d, const uint32_t* a, const uint32_t* b) {
    asm volatile("mma.sync.aligned.m16n8k16.row.col.f32.bf16.bf16.f32 "
                 "{%0,%1,%2,%3}, {%4,%5,%6,%7}, {%8,%9}, {%0,%1,%2,%3};"
                 : "+f"(d[0]), "+f"(d[1]), "+f"(d[2]), "+f"(d[3])
                 : "r"(a[0]), "r"(a[1]), "r"(a[2]), "r"(a[3]), "r"(b[0]), "r"(b[1]));
}
__device__ __forceinline__ void cp16(uint32_t saddr, const void* g) {
    asm volatile("cp.async.cg.shared.global [%0], [%1], 16;" :: "r"(saddr), "l"(g));
}
#define CP_COMMIT() asm volatile("cp.async.commit_group;" ::: "memory")
#define CP_WAIT1()  asm volatile("cp.async.wait_group 1;" ::: "memory")
#define CP_WAIT0()  asm volatile("cp.async.wait_group 0;" ::: "memory")

__device__ __forceinline__ uint32_t bf2u(__nv_bfloat16 a, __nv_bfloat16 b) {
    __nv_bfloat162 t; t.x = a; t.y = b;
    return *reinterpret_cast<uint32_t*>(&t);
}
__device__ __forceinline__ void cvt_hl(float4 v, uint2& hi, uint2& lo) {
    __nv_bfloat16 h0 = __float2bfloat16_rn(v.x);
    __nv_bfloat16 h1 = __float2bfloat16_rn(v.y);
    __nv_bfloat16 h2 = __float2bfloat16_rn(v.z);
    __nv_bfloat16 h3 = __float2bfloat16_rn(v.w);
    __nv_bfloat16 l0 = __float2bfloat16_rn(v.x - __bfloat162float(h0));
    __nv_bfloat16 l1 = __float2bfloat16_rn(v.y - __bfloat162float(h1));
    __nv_bfloat16 l2 = __float2bfloat16_rn(v.z - __bfloat162float(h2));
    __nv_bfloat16 l3 = __float2bfloat16_rn(v.w - __bfloat162float(h3));
    hi = make_uint2(bf2u(h0, h1), bf2u(h2, h3));
    lo = make_uint2(bf2u(l0, l1), bf2u(l2, l3));
}
__device__ __forceinline__ void split2(float a, float b, uint32_t& hi, uint32_t& lo) {
    __nv_bfloat16 h0 = __float2bfloat16_rn(a);
    __nv_bfloat16 h1 = __float2bfloat16_rn(b);
    __nv_bfloat16 l0 = __float2bfloat16_rn(a - __bfloat162float(h0));
    __nv_bfloat16 l1 = __float2bfloat16_rn(b - __bfloat162float(h1));
    hi = bf2u(h0, h1);
    lo = bf2u(l0, l1);
}

// ===========================================================================
// Convert: split x / qkv_w / out_w fp32 -> bf16 hi/lo
// ===========================================================================
#define N4_X  (BSROWS*DM/4)
#define N4_WQ (QKVN*DM/4)
#define N4_WO (DM*DM/4)
#define N4_TOTAL (N4_X + N4_WQ + N4_WO)

__global__ __launch_bounds__(256)
void cvt_split_kernel(const float* __restrict__ x, const float* __restrict__ wq,
                      const float* __restrict__ wo) {
    int i = blockIdx.x * blockDim.x + threadIdx.x;
    const float4* s; uint2 *dh, *dl; int j;
    if (i < N4_X)                  { j = i;                 s = (const float4*)x;  dh = (uint2*)x_hi;  dl = (uint2*)x_lo; }
    else if (i < N4_X + N4_WQ)     { j = i - N4_X;          s = (const float4*)wq; dh = (uint2*)wq_hi; dl = (uint2*)wq_lo; }
    else                           { j = i - N4_X - N4_WQ;  s = (const float4*)wo; dh = (uint2*)wo_hi; dl = (uint2*)wo_lo; }
    float4 v = s[j];
    uint2 h, l;
    cvt_hl(v, h, l);
    dh[j] = h; dl[j] = l;
}

// ===========================================================================
// bf16x3 GEMM via mma.sync + cp.async. C[M,N] = A[M,1024] @ B[N,1024]^T.
// CTA tile 128x128, 8 warps (64x32), K-chunk 32, 2-stage cp.async pipeline.
// MODE 0: store fp32 C. MODE 1: fused RoPE epilogue -> q/k/v hi/lo.
// ===========================================================================
#define KC 32
#define LDAS 40
#define TILE_HL (128 * LDAS * 2)        // 10240 B
#define STAGE_B (4 * TILE_HL)           // 40960 B
#define GEMM_SMEM (2 * STAGE_B)         // 81920 B
#define OFF_AHI 0
#define OFF_ALO TILE_HL
#define OFF_BHI (2*TILE_HL)
#define OFF_BLO (3*TILE_HL)
#define KLOG 0.28782313662f             // 2/64 * ln(10000)

template<int MODE>
__global__ __launch_bounds__(256, 2)
void gemm_bf16x3_kernel(const __nv_bfloat16* __restrict__ Ahi, const __nv_bfloat16* __restrict__ Alo,
                        const __nv_bfloat16* __restrict__ Bhi, const __nv_bfloat16* __restrict__ Blo,
                        float* __restrict__ C, const int* __restrict__ pos, int N) {
    extern __shared__ char smem[];
    const uint32_t sbase = smem_u32(smem);
    const int tid  = threadIdx.x;
    const int wid  = tid >> 5;
    const int lane = tid & 31;
    const int m0 = blockIdx.y * 128;
    const int n0 = blockIdx.x * 128;
    const int wm = wid & 1;
    const int wn = wid >> 1;

    const uint4* Ah4 = (const uint4*)Ahi;
    const uint4* Al4 = (const uint4*)Alo;
    const uint4* Bh4 = (const uint4*)Bhi;
    const uint4* Bl4 = (const uint4*)Blo;

    // chunk issue: 128x32 bf16 per tile, 2 uint4 per thread per array
    int lrow[2], lch[2];
#pragma unroll
    for (int it = 0; it < 2; it++) {
        int f = it * 256 + tid;
        lrow[it] = f >> 2;
        lch[it]  = (f & 3) * 8;
    }
    auto issue = [&](int c, int s) {
        const int k0 = c * KC;
#pragma unroll
        for (int it = 0; it < 2; it++) {
            size_t gi = ((size_t)(m0 + lrow[it]) * DM + k0 + lch[it]) >> 3;
            size_t gj = ((size_t)(n0 + lrow[it]) * DM + k0 + lch[it]) >> 3;
            uint32_t so = sbase + s * STAGE_B + (uint32_t)(lrow[it] * LDAS + lch[it]) * 2;
            cp16(so + OFF_AHI, Ah4 + gi);
            cp16(so + OFF_ALO, Al4 + gi);
            cp16(so + OFF_BHI, Bh4 + gj);
            cp16(so + OFF_BLO, Bl4 + gj);
        }
    };

    const int arow = (lane & 7) + ((lane >> 3) & 1) * 8;
    const int acol = (lane >> 4) * 8;
    const int bl   = lane & 15;
    const int brow = bl & 7;
    const int bk   = (bl >> 3) * 8;

    float acc[4][4][4];
#pragma unroll
    for (int mi = 0; mi < 4; mi++)
#pragma unroll
        for (int ni = 0; ni < 4; ni++)
#pragma unroll
            for (int q = 0; q < 4; q++) acc[mi][ni][q] = 0.0f;

    const int nch = DM / KC;   // 32
    issue(0, 0); CP_COMMIT();
    issue(1, 1); CP_COMMIT();

    for (int c = 0; c < nch; c++) {
        if (c + 1 < nch) CP_WAIT1(); else CP_WAIT0();
        __syncthreads();

        const uint32_t stg = sbase + (c & 1) * STAGE_B;
#pragma unroll
        for (int ks = 0; ks < 2; ks++) {
            uint32_t ah[4][4], al[4][4];
#pragma unroll
            for (int mi = 0; mi < 4; mi++) {
                uint32_t eoff = ((wm * 64 + mi * 16 + arow) * LDAS + ks * 16 + acol) * 2;
                ldsm_x4(ah[mi], stg + OFF_AHI + eoff);
                ldsm_x4(al[mi], stg + OFF_ALO + eoff);
            }
#pragma unroll
            for (int ni = 0; ni < 4; ni++) {
                uint32_t bhf[2], blf[2];
                uint32_t eoff = ((wn * 32 + ni * 8 + brow) * LDAS + ks * 16 + bk) * 2;
                ldsm_x2(bhf, stg + OFF_BHI + eoff);
                ldsm_x2(blf, stg + OFF_BLO + eoff);
#pragma unroll
                for (int mi = 0; mi < 4; mi++) {
                    mma16816(acc[mi][ni], ah[mi], bhf);
                    mma16816(acc[mi][ni], ah[mi], blf);
                    mma16816(acc[mi][ni], al[mi], bhf);
                }
            }
        }
        __syncthreads();
        if (c + 2 < nch) { issue(c + 2, c & 1); CP_COMMIT(); }
    }

    const int crow = lane >> 2;
    const int ccol = (lane & 3) * 2;

    if (MODE == 0) {
#pragma unroll
        for (int mi = 0; mi < 4; mi++) {
            const size_t r0 = (size_t)(m0 + wm * 64 + mi * 16 + crow);
#pragma unroll
            for (int ni = 0; ni < 4; ni++) {
                const int cc = n0 + wn * 32 + ni * 8 + ccol;
                *(float2*)(C + r0 * N + cc)       = make_float2(acc[mi][ni][0], acc[mi][ni][1]);
                *(float2*)(C + (r0 + 8) * N + cc) = make_float2(acc[mi][ni][2], acc[mi][ni][3]);
            }
        }
    } else {
        // fused RoPE: n0 selects section (0=q rope*0.125, 1=k rope, 2=v copy)
        const int sec  = n0 >> 10;
        const int nmod = n0 & 1023;
        int hh_[4], ii_[4];
        float ifr_[4];
#pragma unroll
        for (int ni = 0; ni < 4; ni++) {
            int colmod = nmod + wn * 32 + ni * 8 + ccol;
            hh_[ni] = colmod >> 6;
            ii_[ni] = (colmod & 63) >> 1;
            ifr_[ni] = (sec < 2) ? expf(-(float)ii_[ni] * KLOG) : 0.0f;
        }
        uint32_t* ghi = (sec == 0) ? (uint32_t*)q_hi : (sec == 1) ? (uint32_t*)k_hi : (uint32_t*)v_hi;
        uint32_t* glo = (sec == 0) ? (uint32_t*)q_lo : (sec == 1) ? (uint32_t*)k_lo : (uint32_t*)v_lo;
#pragma unroll
        for (int mi = 0; mi < 4; mi++) {
            const int rbase = m0 + wm * 64 + mi * 16 + crow;
#pragma unroll
            for (int half = 0; half < 2; half++) {
                const int r = rbase + half * 8;
                const int p = pos[r];
                const int b = r >> 11;
                const int s = r & 2047;
#pragma unroll
                for (int ni = 0; ni < 4; ni++) {
                    float v0 = acc[mi][ni][half * 2];
                    float v1 = acc[mi][ni][half * 2 + 1];
                    float o0, o1;
                    if (sec < 2) {
                        float ang = (float)p * ifr_[ni];
                        float cs = cosf(ang), sn = sinf(ang);
                        o0 = v0 * cs - v1 * sn;
                        o1 = v0 * sn + v1 * cs;
                        if (sec == 0) { o0 *= 0.125f; o1 *= 0.125f; }
                    } else { o0 = v0; o1 = v1; }
                    uint32_t hi, lo;
                    split2(o0, o1, hi, lo);
                    size_t idx = ((size_t)(b * HH + hh_[ni]) * SS + s) * 32 + ii_[ni];
                    ghi[idx] = hi;
                    glo[idx] = lo;
                }
            }
        }
    }
}

// ===========================================================================
// Tensor-core causal flash attention (bf16x3), pre-split q/k/v inputs.
// CTA = (bh, 128-q-tile), 8 warps x m16 slabs, kv tiles of 64,
// double-buffered cp.async K/V. Output written pre-split to att_hi/att_lo.
// ===========================================================================
#define AT_LDS 72
#define AT_STG 36864                    // one KV stage: Khi,Klo,Vhi,Vlo @ 9216
#define AT_QHI 73728
#define AT_QLO 92160
#define ATT_SMEM 110592

__global__ __launch_bounds__(256)
void attn_tc_kernel() {
    extern __shared__ char smem[];
    const uint32_t sb = smem_u32(smem);
    const int tid  = threadIdx.x;
    const int wid  = tid >> 5;
    const int lane = tid & 31;
    const int bh = blockIdx.y;
    const int qt = gridDim.x - 1 - blockIdx.x;   // heavy tiles first
    const int qbase = qt * 128;

    const uint4* qh4 = (const uint4*)q_hi + (size_t)bh * SS * 8;
    const uint4* ql4 = (const uint4*)q_lo + (size_t)bh * SS * 8;
    const uint4* kh4 = (const uint4*)k_hi + (size_t)bh * SS * 8;
    const uint4* kl4 = (const uint4*)k_lo + (size_t)bh * SS * 8;
    const uint4* vh4 = (const uint4*)v_hi + (size_t)bh * SS * 8;
    const uint4* vl4 = (const uint4*)v_lo + (size_t)bh * SS * 8;

    // ---- load Q tile 128x64 hi/lo (4 uint4/thread/array) ----
#pragma unroll
    for (int it = 0; it < 4; it++) {
        int f = it * 256 + tid;
        int row = f >> 3;
        int ch  = f & 7;
        uint32_t so = (uint32_t)(row * AT_LDS + ch * 8) * 2;
        *(uint4*)(smem + AT_QHI + so) = qh4[(size_t)(qbase + row) * 8 + ch];
        *(uint4*)(smem + AT_QLO + so) = ql4[(size_t)(qbase + row) * 8 + ch];
    }
    __syncthreads();

    const int arow = (lane & 7) + ((lane >> 3) & 1) * 8;
    const int acol = (lane >> 4) * 8;
    uint32_t qh[4][4], ql[4][4];
#pragma unroll
    for (int ks = 0; ks < 4; ks++) {
        uint32_t eoff = ((wid * 16 + arow) * AT_LDS + ks * 16 + acol) * 2;
        ldsm_x4(qh[ks], sb + AT_QHI + eoff);
        ldsm_x4(ql[ks], sb + AT_QLO + eoff);
    }

    float o[8][4];
#pragma unroll
    for (int ni = 0; ni < 8; ni++)
#pragma unroll
        for (int q = 0; q < 4; q++) o[ni][q] = 0.0f;
    float m0 = -INFINITY, m1 = -INFINITY, l0 = 0.0f, l1 = 0.0f;

    const int g  = lane >> 2;
    const int qq = lane & 3;
    const int row0 = qbase + wid * 16 + g;
    const int warp_maxrow = qbase + wid * 16 + 15;

    const int bl = lane & 15;
    const int brow = bl & 7;
    const int bk = (bl >> 3) * 8;

    // KV tile async loader: 2 uint4/thread/array
    auto kv_issue = [&](int t, int s) {
        const int kvb = t * 64;
#pragma unroll
        for (int it = 0; it < 2; it++) {
            int f = it * 256 + tid;
            int row = f >> 3;
            int ch  = f & 7;
            uint32_t so = sb + s * AT_STG + (uint32_t)(row * AT_LDS + ch * 8) * 2;
            size_t gi = (size_t)(kvb + row) * 8 + ch;
            cp16(so,         kh4 + gi);
            cp16(so +  9216, kl4 + gi);
            cp16(so + 18432, vh4 + gi);
            cp16(so + 27648, vl4 + gi);
        }
    };

    const int ntiles = (qt + 1) * 2;
    kv_issue(0, 0); CP_COMMIT();

    for (int t = 0; t < ntiles; t++) {
        if (t + 1 < ntiles) { kv_issue(t + 1, (t + 1) & 1); CP_COMMIT(); CP_WAIT1(); }
        else CP_WAIT0();
        __syncthreads();

        const int kvb = t * 64;
        const uint32_t stg = sb + (t & 1) * AT_STG;

        if (kvb <= warp_maxrow) {
            // ---- S = Q @ K^T (3-term) ----
            float s[8][4];
#pragma unroll
            for (int ni = 0; ni < 8; ni++)
#pragma unroll
                for (int q = 0; q < 4; q++) s[ni][q] = 0.0f;
#pragma unroll
            for (int ks = 0; ks < 4; ks++) {
#pragma unroll
                for (int ni = 0; ni < 8; ni++) {
                    uint32_t khf[2], klf[2];
                    uint32_t eoff = ((ni * 8 + brow) * AT_LDS + ks * 16 + bk) * 2;
                    ldsm_x2(khf, stg + eoff);
                    ldsm_x2(klf, stg + 9216 + eoff);
                    mma16816(s[ni], qh[ks], khf);
                    mma16816(s[ni], qh[ks], klf);
                    mma16816(s[ni], ql[ks], khf);
                }
            }

            // ---- causal mask ----
            if (kvb + 63 > qbase + wid * 16) {
#pragma unroll
                for (int ni = 0; ni < 8; ni++) {
                    int c = kvb + ni * 8 + qq * 2;
                    if (c     > row0)     s[ni][0] = -INFINITY;
                    if (c + 1 > row0)     s[ni][1] = -INFINITY;
                    if (c     > row0 + 8) s[ni][2] = -INFINITY;
                    if (c + 1 > row0 + 8) s[ni][3] = -INFINITY;
                }
            }

            // ---- online softmax ----
            float t0 = -INFINITY, t1 = -INFINITY;
#pragma unroll
            for (int ni = 0; ni < 8; ni++) {
                t0 = fmaxf(t0, fmaxf(s[ni][0], s[ni][1]));
                t1 = fmaxf(t1, fmaxf(s[ni][2], s[ni][3]));
            }
            t0 = fmaxf(t0, __shfl_xor_sync(0xFFFFFFFF, t0, 1));
            t0 = fmaxf(t0, __shfl_xor_sync(0xFFFFFFFF, t0, 2));
            t1 = fmaxf(t1, __shfl_xor_sync(0xFFFFFFFF, t1, 1));
            t1 = fmaxf(t1, __shfl_xor_sync(0xFFFFFFFF, t1, 2));
            float nm0 = fmaxf(m0, t0), nm1 = fmaxf(m1, t1);
            float sc0 = __expf(m0 - nm0), sc1 = __expf(m1 - nm1);
            m0 = nm0; m1 = nm1;
            l0 *= sc0; l1 *= sc1;
#pragma unroll
            for (int ni = 0; ni < 8; ni++) {
                o[ni][0] *= sc0; o[ni][1] *= sc0;
                o[ni][2] *= sc1; o[ni][3] *= sc1;
            }

            // ---- P = exp(S - m) -> bf16 hi/lo A-fragments ----
            uint32_t ph[8][2], pl[8][2];
            float rs0 = 0.0f, rs1 = 0.0f;
#pragma unroll
            for (int ni = 0; ni < 8; ni++) {
                float p0 = __expf(s[ni][0] - m0);
                float p1 = __expf(s[ni][1] - m0);
                float p2 = __expf(s[ni][2] - m1);
                float p3 = __expf(s[ni][3] - m1);
                rs0 += p0 + p1;
                rs1 += p2 + p3;
                split2(p0, p1, ph[ni][0], pl[ni][0]);
                split2(p2, p3, ph[ni][1], pl[ni][1]);
            }
            rs0 += __shfl_xor_sync(0xFFFFFFFF, rs0, 1);
            rs0 += __shfl_xor_sync(0xFFFFFFFF, rs0, 2);
            rs1 += __shfl_xor_sync(0xFFFFFFFF, rs1, 1);
            rs1 += __shfl_xor_sync(0xFFFFFFFF, rs1, 2);
            l0 += rs0; l1 += rs1;

            // ---- O += P @ V (3-term); V via ldmatrix.trans ----
#pragma unroll
            for (int kc = 0; kc < 4; kc++) {
                uint32_t ah[4] = { ph[2*kc][0], ph[2*kc][1], ph[2*kc+1][0], ph[2*kc+1][1] };
                uint32_t al[4] = { pl[2*kc][0], pl[2*kc][1], pl[2*kc+1][0], pl[2*kc+1][1] };
#pragma unroll
                for (int ni = 0; ni < 8; ni++) {
                    uint32_t vhf[2], vlf[2];
                    uint32_t eoff = ((kc * 16 + bl) * AT_LDS + ni * 8) * 2;
                    ldsm_x2t(vhf, stg + 18432 + eoff);
                    ldsm_x2t(vlf, stg + 27648 + eoff);
                    mma16816(o[ni], ah, vhf);
                    mma16816(o[ni], ah, vlf);
                    mma16816(o[ni], al, vhf);
                }
            }
        }
        __syncthreads();
    }

    // ---- epilogue: normalize + split -> att_hi/att_lo ----
    const float inv0 = 1.0f / l0;
    const float inv1 = 1.0f / l1;
    const int b = bh / HH;
    const int h = bh % HH;
    uint32_t* ahi32 = (uint32_t*)att_hi;
    uint32_t* alo32 = (uint32_t*)att_lo;
    const size_t base0 = ((size_t)b * SS + row0) * 512 + h * 32;
    const size_t base1 = ((size_t)b * SS + row0 + 8) * 512 + h * 32;
#pragma unroll
    for (int ni = 0; ni < 8; ni++) {
        uint32_t hi, lo;
        split2(o[ni][0] * inv0, o[ni][1] * inv0, hi, lo);
        ahi32[base0 + ni * 4 + qq] = hi;
        alo32[base0 + ni * 4 + qq] = lo;
        split2(o[ni][2] * inv1, o[ni][3] * inv1, hi, lo);
        ahi32[base1 + ni * 4 + qq] = hi;
        alo32[base1 + ni * 4 + qq] = lo;
    }
}

// ===========================================================================
extern "C" void kernel_launch(void* const* d_in, const int* in_sizes, int n_in,
                              void* d_out, int out_size) {
    const float* x     = (const float*)d_in[0];
    const int*   pos   = (const int*)d_in[1];
    const float* qkv_w = (const float*)d_in[2];
    const float* out_w = (const float*)d_in[3];
    float* out = (float*)d_out;

    __nv_bfloat16 *p_xhi, *p_xlo, *p_wqhi, *p_wqlo, *p_wohi, *p_wolo, *p_ahi, *p_alo;
    cudaGetSymbolAddress((void**)&p_xhi,  x_hi);
    cudaGetSymbolAddress((void**)&p_xlo,  x_lo);
    cudaGetSymbolAddress((void**)&p_wqhi, wq_hi);
    cudaGetSymbolAddress((void**)&p_wqlo, wq_lo);
    cudaGetSymbolAddress((void**)&p_wohi, wo_hi);
    cudaGetSymbolAddress((void**)&p_wolo, wo_lo);
    cudaGetSymbolAddress((void**)&p_ahi,  att_hi);
    cudaGetSymbolAddress((void**)&p_alo,  att_lo);

    cudaFuncSetAttribute(gemm_bf16x3_kernel<0>, cudaFuncAttributeMaxDynamicSharedMemorySize, GEMM_SMEM);
    cudaFuncSetAttribute(gemm_bf16x3_kernel<1>, cudaFuncAttributeMaxDynamicSharedMemorySize, GEMM_SMEM);
    cudaFuncSetAttribute(attn_tc_kernel,        cudaFuncAttributeMaxDynamicSharedMemorySize, ATT_SMEM);

    // 0) fp32 -> bf16 hi/lo for x, qkv_w, out_w
    cvt_split_kernel<<<N4_TOTAL / 256, 256>>>(x, qkv_w, out_w);

    // 1) QKV projection + fused RoPE -> q/k/v hi/lo
    gemm_bf16x3_kernel<1><<<dim3(QKVN / 128, BSROWS / 128), 256, GEMM_SMEM>>>(
        p_xhi, p_xlo, p_wqhi, p_wqlo, nullptr, pos, QKVN);

    // 2) Causal flash attention -> att hi/lo
    attn_tc_kernel<<<dim3(SS / 128, BB * HH), 256, ATT_SMEM>>>();

    // 3) Output projection -> fp32 out
    gemm_bf16x3_kernel<0><<<dim3(DM / 128, BSROWS / 128), 256, GEMM_SMEM>>>(
        p_ahi, p_alo, p_wohi, p_wolo, out, nullptr, DM);
}

// round 10
// speedup vs baseline: 3.5320x; 1.0755x over previous
#include <cuda_runtime.h>
#include <cuda_bf16.h>
#include <math.h>
#include <stdint.h>

#define BB 2
#define SS 2048
#define DM 1024
#define HH 16
#define DK 64
#define BSROWS (BB*SS)      // 4096
#define QKVN (3*DM)         // 3072

// ===========================================================================
// Scratch (allocation-free rule: __device__ globals). Everything bf16 hi/lo.
// ===========================================================================
__device__ __align__(16) __nv_bfloat16 x_hi[(size_t)BSROWS*DM];
__device__ __align__(16) __nv_bfloat16 x_lo[(size_t)BSROWS*DM];
__device__ __align__(16) __nv_bfloat16 wq_hi[(size_t)QKVN*DM];
__device__ __align__(16) __nv_bfloat16 wq_lo[(size_t)QKVN*DM];
__device__ __align__(16) __nv_bfloat16 wo_hi[(size_t)DM*DM];
__device__ __align__(16) __nv_bfloat16 wo_lo[(size_t)DM*DM];
__device__ __align__(16) __nv_bfloat16 q_hi[(size_t)BB*HH*SS*DK];
__device__ __align__(16) __nv_bfloat16 q_lo[(size_t)BB*HH*SS*DK];
__device__ __align__(16) __nv_bfloat16 k_hi[(size_t)BB*HH*SS*DK];
__device__ __align__(16) __nv_bfloat16 k_lo[(size_t)BB*HH*SS*DK];
__device__ __align__(16) __nv_bfloat16 v_hi[(size_t)BB*HH*SS*DK];
__device__ __align__(16) __nv_bfloat16 v_lo[(size_t)BB*HH*SS*DK];
__device__ __align__(16) __nv_bfloat16 att_hi[(size_t)BSROWS*DM];
__device__ __align__(16) __nv_bfloat16 att_lo[(size_t)BSROWS*DM];

// ===========================================================================
// PTX helpers
// ===========================================================================
__device__ __forceinline__ uint32_t smem_u32(const void* p) {
    uint32_t a;
    asm("{ .reg .u64 t; cvta.to.shared.u64 t, %1; cvt.u32.u64 %0, t; }" : "=r"(a) : "l"(p));
    return a;
}
__device__ __forceinline__ void ldsm_x4(uint32_t* r, uint32_t addr) {
    asm volatile("ldmatrix.sync.aligned.m8n8.x4.shared.b16 {%0,%1,%2,%3}, [%4];"
                 : "=r"(r[0]), "=r"(r[1]), "=r"(r[2]), "=r"(r[3]) : "r"(addr));
}
__device__ __forceinline__ void ldsm_x4t(uint32_t* r, uint32_t addr) {
    asm volatile("ldmatrix.sync.aligned.m8n8.x4.trans.shared.b16 {%0,%1,%2,%3}, [%4];"
                 : "=r"(r[0]), "=r"(r[1]), "=r"(r[2]), "=r"(r[3]) : "r"(addr));
}
__device__ __forceinline__ void mma16816(float* d, const uint32_t* a, const uint32_t* b) {
    asm volatile("mma.sync.aligned.m16n8k16.row.col.f32.bf16.bf16.f32 "
                 "{%0,%1,%2,%3}, {%4,%5,%6,%7}, {%8,%9}, {%0,%1,%2,%3};"
                 : "+f"(d[0]), "+f"(d[1]), "+f"(d[2]), "+f"(d[3])
                 : "r"(a[0]), "r"(a[1]), "r"(a[2]), "r"(a[3]), "r"(b[0]), "r"(b[1]));
}
__device__ __forceinline__ void cp16(uint32_t saddr, const void* g) {
    asm volatile("cp.async.cg.shared.global [%0], [%1], 16;" :: "r"(saddr), "l"(g));
}
#define CP_COMMIT() asm volatile("cp.async.commit_group;" ::: "memory")
#define CP_WAIT2()  asm volatile("cp.async.wait_group 2;" ::: "memory")
#define CP_WAIT1()  asm volatile("cp.async.wait_group 1;" ::: "memory")
#define CP_WAIT0()  asm volatile("cp.async.wait_group 0;" ::: "memory")

__device__ __forceinline__ uint32_t bf2u(__nv_bfloat16 a, __nv_bfloat16 b) {
    __nv_bfloat162 t; t.x = a; t.y = b;
    return *reinterpret_cast<uint32_t*>(&t);
}
__device__ __forceinline__ void cvt_hl(float4 v, uint2& hi, uint2& lo) {
    __nv_bfloat16 h0 = __float2bfloat16_rn(v.x);
    __nv_bfloat16 h1 = __float2bfloat16_rn(v.y);
    __nv_bfloat16 h2 = __float2bfloat16_rn(v.z);
    __nv_bfloat16 h3 = __float2bfloat16_rn(v.w);
    __nv_bfloat16 l0 = __float2bfloat16_rn(v.x - __bfloat162float(h0));
    __nv_bfloat16 l1 = __float2bfloat16_rn(v.y - __bfloat162float(h1));
    __nv_bfloat16 l2 = __float2bfloat16_rn(v.z - __bfloat162float(h2));
    __nv_bfloat16 l3 = __float2bfloat16_rn(v.w - __bfloat162float(h3));
    hi = make_uint2(bf2u(h0, h1), bf2u(h2, h3));
    lo = make_uint2(bf2u(l0, l1), bf2u(l2, l3));
}
__device__ __forceinline__ void split2(float a, float b, uint32_t& hi, uint32_t& lo) {
    __nv_bfloat16 h0 = __float2bfloat16_rn(a);
    __nv_bfloat16 h1 = __float2bfloat16_rn(b);
    __nv_bfloat16 l0 = __float2bfloat16_rn(a - __bfloat162float(h0));
    __nv_bfloat16 l1 = __float2bfloat16_rn(b - __bfloat162float(h1));
    hi = bf2u(h0, h1);
    lo = bf2u(l0, l1);
}

// ===========================================================================
// Convert: split x / qkv_w / out_w fp32 -> bf16 hi/lo
// ===========================================================================
#define N4_X  (BSROWS*DM/4)
#define N4_WQ (QKVN*DM/4)
#define N4_WO (DM*DM/4)
#define N4_TOTAL (N4_X + N4_WQ + N4_WO)

__global__ __launch_bounds__(256)
void cvt_split_kernel(const float* __restrict__ x, const float* __restrict__ wq,
                      const float* __restrict__ wo) {
    int i = blockIdx.x * blockDim.x + threadIdx.x;
    const float4* s; uint2 *dh, *dl; int j;
    if (i < N4_X)                  { j = i;                 s = (const float4*)x;  dh = (uint2*)x_hi;  dl = (uint2*)x_lo; }
    else if (i < N4_X + N4_WQ)     { j = i - N4_X;          s = (const float4*)wq; dh = (uint2*)wq_hi; dl = (uint2*)wq_lo; }
    else                           { j = i - N4_X - N4_WQ;  s = (const float4*)wo; dh = (uint2*)wo_hi; dl = (uint2*)wo_lo; }
    float4 v = s[j];
    uint2 h, l;
    cvt_hl(v, h, l);
    dh[j] = h; dl[j] = l;
}

// ===========================================================================
// bf16x3 GEMM via mma.sync + cp.async. C[M,N] = A[M,1024] @ B[N,1024]^T.
// CTA tile 128x128, 8 warps (64x32), K-chunk 32, 2-stage cp.async pipeline.
// B fragments via ldmatrix.x4 pairing (two n8 blocks per instruction).
// MODE 0: store fp32 C. MODE 1: fused RoPE epilogue -> q/k/v hi/lo.
// ===========================================================================
#define KC 32
#define LDAS 40
#define TILE_HL (128 * LDAS * 2)        // 10240 B
#define STAGE_B (4 * TILE_HL)           // 40960 B
#define GEMM_SMEM (2 * STAGE_B)         // 81920 B
#define OFF_AHI 0
#define OFF_ALO TILE_HL
#define OFF_BHI (2*TILE_HL)
#define OFF_BLO (3*TILE_HL)
#define KLOG 0.28782313662f             // 2/64 * ln(10000)

template<int MODE>
__global__ __launch_bounds__(256, 2)
void gemm_bf16x3_kernel(const __nv_bfloat16* __restrict__ Ahi, const __nv_bfloat16* __restrict__ Alo,
                        const __nv_bfloat16* __restrict__ Bhi, const __nv_bfloat16* __restrict__ Blo,
                        float* __restrict__ C, const int* __restrict__ pos, int N) {
    extern __shared__ char smem[];
    const uint32_t sbase = smem_u32(smem);
    const int tid  = threadIdx.x;
    const int wid  = tid >> 5;
    const int lane = tid & 31;
    const int m0 = blockIdx.y * 128;
    const int n0 = blockIdx.x * 128;
    const int wm = wid & 1;
    const int wn = wid >> 1;

    const uint4* Ah4 = (const uint4*)Ahi;
    const uint4* Al4 = (const uint4*)Alo;
    const uint4* Bh4 = (const uint4*)Bhi;
    const uint4* Bl4 = (const uint4*)Blo;

    int lrow[2], lch[2];
#pragma unroll
    for (int it = 0; it < 2; it++) {
        int f = it * 256 + tid;
        lrow[it] = f >> 2;
        lch[it]  = (f & 3) * 8;
    }
    auto issue = [&](int c, int s) {
        const int k0 = c * KC;
#pragma unroll
        for (int it = 0; it < 2; it++) {
            size_t gi = ((size_t)(m0 + lrow[it]) * DM + k0 + lch[it]) >> 3;
            size_t gj = ((size_t)(n0 + lrow[it]) * DM + k0 + lch[it]) >> 3;
            uint32_t so = sbase + s * STAGE_B + (uint32_t)(lrow[it] * LDAS + lch[it]) * 2;
            cp16(so + OFF_AHI, Ah4 + gi);
            cp16(so + OFF_ALO, Al4 + gi);
            cp16(so + OFF_BHI, Bh4 + gj);
            cp16(so + OFF_BLO, Bl4 + gj);
        }
    };

    // ldmatrix lane addressing
    const int gg   = lane >> 3;                         // group 0..3
    const int arow = (lane & 7) + ((lane >> 3) & 1) * 8;
    const int acol = (lane >> 4) * 8;
    // B x4 pairing: g0:(n0-7,k0) g1:(n0-7,k8) g2:(n8-15,k0) g3:(n8-15,k8)
    const int b4row = ((gg >> 1) & 1) * 8 + (lane & 7);
    const int b4col = (gg & 1) * 8;

    float acc[4][4][4];
#pragma unroll
    for (int mi = 0; mi < 4; mi++)
#pragma unroll
        for (int ni = 0; ni < 4; ni++)
#pragma unroll
            for (int q = 0; q < 4; q++) acc[mi][ni][q] = 0.0f;

    const int nch = DM / KC;   // 32
    issue(0, 0); CP_COMMIT();
    issue(1, 1); CP_COMMIT();

    for (int c = 0; c < nch; c++) {
        if (c + 1 < nch) CP_WAIT1(); else CP_WAIT0();
        __syncthreads();

        const uint32_t stg = sbase + (c & 1) * STAGE_B;
#pragma unroll
        for (int ks = 0; ks < 2; ks++) {
            uint32_t ah[4][4], al[4][4];
#pragma unroll
            for (int mi = 0; mi < 4; mi++) {
                uint32_t eoff = ((wm * 64 + mi * 16 + arow) * LDAS + ks * 16 + acol) * 2;
                ldsm_x4(ah[mi], stg + OFF_AHI + eoff);
                ldsm_x4(al[mi], stg + OFF_ALO + eoff);
            }
#pragma unroll
            for (int n2 = 0; n2 < 2; n2++) {
                uint32_t bhf[4], blf[4];
                uint32_t eoff = ((wn * 32 + n2 * 16 + b4row) * LDAS + ks * 16 + b4col) * 2;
                ldsm_x4(bhf, stg + OFF_BHI + eoff);
                ldsm_x4(blf, stg + OFF_BLO + eoff);
#pragma unroll
                for (int mi = 0; mi < 4; mi++) {
                    mma16816(acc[mi][n2 * 2],     ah[mi], bhf);
                    mma16816(acc[mi][n2 * 2],     ah[mi], blf);
                    mma16816(acc[mi][n2 * 2],     al[mi], bhf);
                    mma16816(acc[mi][n2 * 2 + 1], ah[mi], bhf + 2);
                    mma16816(acc[mi][n2 * 2 + 1], ah[mi], blf + 2);
                    mma16816(acc[mi][n2 * 2 + 1], al[mi], bhf + 2);
                }
            }
        }
        __syncthreads();
        if (c + 2 < nch) { issue(c + 2, c & 1); CP_COMMIT(); }
    }

    const int crow = lane >> 2;
    const int ccol = (lane & 3) * 2;

    if (MODE == 0) {
#pragma unroll
        for (int mi = 0; mi < 4; mi++) {
            const size_t r0 = (size_t)(m0 + wm * 64 + mi * 16 + crow);
#pragma unroll
            for (int ni = 0; ni < 4; ni++) {
                const int cc = n0 + wn * 32 + ni * 8 + ccol;
                *(float2*)(C + r0 * N + cc)       = make_float2(acc[mi][ni][0], acc[mi][ni][1]);
                *(float2*)(C + (r0 + 8) * N + cc) = make_float2(acc[mi][ni][2], acc[mi][ni][3]);
            }
        }
    } else {
        const int sec  = n0 >> 10;
        const int nmod = n0 & 1023;
        int hh_[4], ii_[4];
        float ifr_[4];
#pragma unroll
        for (int ni = 0; ni < 4; ni++) {
            int colmod = nmod + wn * 32 + ni * 8 + ccol;
            hh_[ni] = colmod >> 6;
            ii_[ni] = (colmod & 63) >> 1;
            ifr_[ni] = (sec < 2) ? expf(-(float)ii_[ni] * KLOG) : 0.0f;
        }
        uint32_t* ghi = (sec == 0) ? (uint32_t*)q_hi : (sec == 1) ? (uint32_t*)k_hi : (uint32_t*)v_hi;
        uint32_t* glo = (sec == 0) ? (uint32_t*)q_lo : (sec == 1) ? (uint32_t*)k_lo : (uint32_t*)v_lo;
#pragma unroll
        for (int mi = 0; mi < 4; mi++) {
            const int rbase = m0 + wm * 64 + mi * 16 + crow;
#pragma unroll
            for (int half = 0; half < 2; half++) {
                const int r = rbase + half * 8;
                const int p = pos[r];
                const int b = r >> 11;
                const int s = r & 2047;
#pragma unroll
                for (int ni = 0; ni < 4; ni++) {
                    float v0 = acc[mi][ni][half * 2];
                    float v1 = acc[mi][ni][half * 2 + 1];
                    float o0, o1;
                    if (sec < 2) {
                        float ang = (float)p * ifr_[ni];
                        float cs = cosf(ang), sn = sinf(ang);
                        o0 = v0 * cs - v1 * sn;
                        o1 = v0 * sn + v1 * cs;
                        if (sec == 0) { o0 *= 0.125f; o1 *= 0.125f; }
                    } else { o0 = v0; o1 = v1; }
                    uint32_t hi, lo;
                    split2(o0, o1, hi, lo);
                    size_t idx = ((size_t)(b * HH + hh_[ni]) * SS + s) * 32 + ii_[ni];
                    ghi[idx] = hi;
                    glo[idx] = lo;
                }
            }
        }
    }
}

// ===========================================================================
// Tensor-core causal flash attention (bf16x3), pre-split q/k/v, 3-stage
// cp.async KV pipeline, x4 ldmatrix for K (pairs) and V (trans pairs).
// ===========================================================================
#define AT_LDS 72
#define AT_STG 36864                    // KV stage: Khi,Klo,Vhi,Vlo @ 9216
#define AT_QHI (3*AT_STG)               // 110592
#define AT_QLO (AT_QHI + 18432)
#define ATT_SMEM (AT_QLO + 18432)       // 147456

__global__ __launch_bounds__(256)
void attn_tc_kernel() {
    extern __shared__ char smem[];
    const uint32_t sb = smem_u32(smem);
    const int tid  = threadIdx.x;
    const int wid  = tid >> 5;
    const int lane = tid & 31;
    const int bh = blockIdx.y;
    const int qt = gridDim.x - 1 - blockIdx.x;   // heavy tiles first
    const int qbase = qt * 128;

    const uint4* qh4 = (const uint4*)q_hi + (size_t)bh * SS * 8;
    const uint4* ql4 = (const uint4*)q_lo + (size_t)bh * SS * 8;
    const uint4* kh4 = (const uint4*)k_hi + (size_t)bh * SS * 8;
    const uint4* kl4 = (const uint4*)k_lo + (size_t)bh * SS * 8;
    const uint4* vh4 = (const uint4*)v_hi + (size_t)bh * SS * 8;
    const uint4* vl4 = (const uint4*)v_lo + (size_t)bh * SS * 8;

    // ---- load Q tile 128x64 hi/lo ----
#pragma unroll
    for (int it = 0; it < 4; it++) {
        int f = it * 256 + tid;
        int row = f >> 3;
        int ch  = f & 7;
        uint32_t so = (uint32_t)(row * AT_LDS + ch * 8) * 2;
        *(uint4*)(smem + AT_QHI + so) = qh4[(size_t)(qbase + row) * 8 + ch];
        *(uint4*)(smem + AT_QLO + so) = ql4[(size_t)(qbase + row) * 8 + ch];
    }
    __syncthreads();

    const int gg   = lane >> 3;
    const int arow = (lane & 7) + ((lane >> 3) & 1) * 8;
    const int acol = (lane >> 4) * 8;
    const int b4row = ((gg >> 1) & 1) * 8 + (lane & 7);   // K x4 pairing
    const int b4col = (gg & 1) * 8;
    const int v4row = (gg & 1) * 8 + (lane & 7);          // V x4t pairing
    const int v4col = (gg >> 1) * 8;

    uint32_t qh[4][4], ql[4][4];
#pragma unroll
    for (int ks = 0; ks < 4; ks++) {
        uint32_t eoff = ((wid * 16 + arow) * AT_LDS + ks * 16 + acol) * 2;
        ldsm_x4(qh[ks], sb + AT_QHI + eoff);
        ldsm_x4(ql[ks], sb + AT_QLO + eoff);
    }

    float o[8][4];
#pragma unroll
    for (int ni = 0; ni < 8; ni++)
#pragma unroll
        for (int q = 0; q < 4; q++) o[ni][q] = 0.0f;
    float m0 = -INFINITY, m1 = -INFINITY, l0 = 0.0f, l1 = 0.0f;

    const int g  = lane >> 2;
    const int qq = lane & 3;
    const int row0 = qbase + wid * 16 + g;
    const int warp_maxrow = qbase + wid * 16 + 15;

    auto kv_issue = [&](int t, int s) {
        const int kvb = t * 64;
#pragma unroll
        for (int it = 0; it < 2; it++) {
            int f = it * 256 + tid;
            int row = f >> 3;
            int ch  = f & 7;
            uint32_t so = sb + s * AT_STG + (uint32_t)(row * AT_LDS + ch * 8) * 2;
            size_t gi = (size_t)(kvb + row) * 8 + ch;
            cp16(so,         kh4 + gi);
            cp16(so +  9216, kl4 + gi);
            cp16(so + 18432, vh4 + gi);
            cp16(so + 27648, vl4 + gi);
        }
    };

    const int ntiles = (qt + 1) * 2;
    kv_issue(0, 0); CP_COMMIT();
    if (ntiles > 1) { kv_issue(1, 1); CP_COMMIT(); }

    int stg_i = 0;
    for (int t = 0; t < ntiles; t++) {
        if (t + 2 < ntiles) {
            int s2 = (stg_i + 2) % 3;
            kv_issue(t + 2, s2); CP_COMMIT();
            CP_WAIT2();
        } else if (t + 1 < ntiles) CP_WAIT1();
        else CP_WAIT0();
        __syncthreads();

        const int kvb = t * 64;
        const uint32_t stg = sb + stg_i * AT_STG;

        if (kvb <= warp_maxrow) {
            // ---- S = Q @ K^T (3-term), K frags via x4 pairs ----
            float s[8][4];
#pragma unroll
            for (int ni = 0; ni < 8; ni++)
#pragma unroll
                for (int q = 0; q < 4; q++) s[ni][q] = 0.0f;
#pragma unroll
            for (int ks = 0; ks < 4; ks++) {
#pragma unroll
                for (int n2 = 0; n2 < 4; n2++) {
                    uint32_t khf[4], klf[4];
                    uint32_t eoff = ((n2 * 16 + b4row) * AT_LDS + ks * 16 + b4col) * 2;
                    ldsm_x4(khf, stg + eoff);
                    ldsm_x4(klf, stg + 9216 + eoff);
                    mma16816(s[n2 * 2],     qh[ks], khf);
                    mma16816(s[n2 * 2],     qh[ks], klf);
                    mma16816(s[n2 * 2],     ql[ks], khf);
                    mma16816(s[n2 * 2 + 1], qh[ks], khf + 2);
                    mma16816(s[n2 * 2 + 1], qh[ks], klf + 2);
                    mma16816(s[n2 * 2 + 1], ql[ks], khf + 2);
                }
            }

            // ---- causal mask ----
            if (kvb + 63 > qbase + wid * 16) {
#pragma unroll
                for (int ni = 0; ni < 8; ni++) {
                    int c = kvb + ni * 8 + qq * 2;
                    if (c     > row0)     s[ni][0] = -INFINITY;
                    if (c + 1 > row0)     s[ni][1] = -INFINITY;
                    if (c     > row0 + 8) s[ni][2] = -INFINITY;
                    if (c + 1 > row0 + 8) s[ni][3] = -INFINITY;
                }
            }

            // ---- online softmax ----
            float t0 = -INFINITY, t1 = -INFINITY;
#pragma unroll
            for (int ni = 0; ni < 8; ni++) {
                t0 = fmaxf(t0, fmaxf(s[ni][0], s[ni][1]));
                t1 = fmaxf(t1, fmaxf(s[ni][2], s[ni][3]));
            }
            t0 = fmaxf(t0, __shfl_xor_sync(0xFFFFFFFF, t0, 1));
            t0 = fmaxf(t0, __shfl_xor_sync(0xFFFFFFFF, t0, 2));
            t1 = fmaxf(t1, __shfl_xor_sync(0xFFFFFFFF, t1, 1));
            t1 = fmaxf(t1, __shfl_xor_sync(0xFFFFFFFF, t1, 2));
            float nm0 = fmaxf(m0, t0), nm1 = fmaxf(m1, t1);
            float sc0 = __expf(m0 - nm0), sc1 = __expf(m1 - nm1);
            m0 = nm0; m1 = nm1;
            l0 *= sc0; l1 *= sc1;
#pragma unroll
            for (int ni = 0; ni < 8; ni++) {
                o[ni][0] *= sc0; o[ni][1] *= sc0;
                o[ni][2] *= sc1; o[ni][3] *= sc1;
            }

            // ---- P = exp(S - m) -> bf16 hi/lo fragments ----
            uint32_t ph[8][2], pl[8][2];
            float rs0 = 0.0f, rs1 = 0.0f;
#pragma unroll
            for (int ni = 0; ni < 8; ni++) {
                float p0 = __expf(s[ni][0] - m0);
                float p1 = __expf(s[ni][1] - m0);
                float p2 = __expf(s[ni][2] - m1);
                float p3 = __expf(s[ni][3] - m1);
                rs0 += p0 + p1;
                rs1 += p2 + p3;
                split2(p0, p1, ph[ni][0], pl[ni][0]);
                split2(p2, p3, ph[ni][1], pl[ni][1]);
            }
            rs0 += __shfl_xor_sync(0xFFFFFFFF, rs0, 1);
            rs0 += __shfl_xor_sync(0xFFFFFFFF, rs0, 2);
            rs1 += __shfl_xor_sync(0xFFFFFFFF, rs1, 1);
            rs1 += __shfl_xor_sync(0xFFFFFFFF, rs1, 2);
            l0 += rs0; l1 += rs1;

            // ---- O += P @ V (3-term); V frags via x4.trans pairs ----
#pragma unroll
            for (int kc = 0; kc < 4; kc++) {
                uint32_t ah[4] = { ph[2*kc][0], ph[2*kc][1], ph[2*kc+1][0], ph[2*kc+1][1] };
                uint32_t al[4] = { pl[2*kc][0], pl[2*kc][1], pl[2*kc+1][0], pl[2*kc+1][1] };
#pragma unroll
                for (int n2 = 0; n2 < 4; n2++) {
                    uint32_t vhf[4], vlf[4];
                    uint32_t eoff = ((kc * 16 + v4row) * AT_LDS + n2 * 16 + v4col) * 2;
                    ldsm_x4t(vhf, stg + 18432 + eoff);
                    ldsm_x4t(vlf, stg + 27648 + eoff);
                    mma16816(o[n2 * 2],     ah, vhf);
                    mma16816(o[n2 * 2],     ah, vlf);
                    mma16816(o[n2 * 2],     al, vhf);
                    mma16816(o[n2 * 2 + 1], ah, vhf + 2);
                    mma16816(o[n2 * 2 + 1], ah, vlf + 2);
                    mma16816(o[n2 * 2 + 1], al, vhf + 2);
                }
            }
        }
        __syncthreads();
        stg_i = (stg_i + 1) % 3;
    }

    // ---- epilogue: normalize + split -> att_hi/att_lo ----
    const float inv0 = 1.0f / l0;
    const float inv1 = 1.0f / l1;
    const int b = bh / HH;
    const int h = bh % HH;
    uint32_t* ahi32 = (uint32_t*)att_hi;
    uint32_t* alo32 = (uint32_t*)att_lo;
    const size_t base0 = ((size_t)b * SS + row0) * 512 + h * 32;
    const size_t base1 = ((size_t)b * SS + row0 + 8) * 512 + h * 32;
#pragma unroll
    for (int ni = 0; ni < 8; ni++) {
        uint32_t hi, lo;
        split2(o[ni][0] * inv0, o[ni][1] * inv0, hi, lo);
        ahi32[base0 + ni * 4 + qq] = hi;
        alo32[base0 + ni * 4 + qq] = lo;
        split2(o[ni][2] * inv1, o[ni][3] * inv1, hi, lo);
        ahi32[base1 + ni * 4 + qq] = hi;
        alo32[base1 + ni * 4 + qq] = lo;
    }
}

// ===========================================================================
extern "C" void kernel_launch(void* const* d_in, const int* in_sizes, int n_in,
                              void* d_out, int out_size) {
    const float* x     = (const float*)d_in[0];
    const int*   pos   = (const int*)d_in[1];
    const float* qkv_w = (const float*)d_in[2];
    const float* out_w = (const float*)d_in[3];
    float* out = (float*)d_out;

    __nv_bfloat16 *p_xhi, *p_xlo, *p_wqhi, *p_wqlo, *p_wohi, *p_wolo, *p_ahi, *p_alo;
    cudaGetSymbolAddress((void**)&p_xhi,  x_hi);
    cudaGetSymbolAddress((void**)&p_xlo,  x_lo);
    cudaGetSymbolAddress((void**)&p_wqhi, wq_hi);
    cudaGetSymbolAddress((void**)&p_wqlo, wq_lo);
    cudaGetSymbolAddress((void**)&p_wohi, wo_hi);
    cudaGetSymbolAddress((void**)&p_wolo, wo_lo);
    cudaGetSymbolAddress((void**)&p_ahi,  att_hi);
    cudaGetSymbolAddress((void**)&p_alo,  att_lo);

    cudaFuncSetAttribute(gemm_bf16x3_kernel<0>, cudaFuncAttributeMaxDynamicSharedMemorySize, GEMM_SMEM);
    cudaFuncSetAttribute(gemm_bf16x3_kernel<1>, cudaFuncAttributeMaxDynamicSharedMemorySize, GEMM_SMEM);
    cudaFuncSetAttribute(attn_tc_kernel,        cudaFuncAttributeMaxDynamicSharedMemorySize, ATT_SMEM);

    // 0) fp32 -> bf16 hi/lo for x, qkv_w, out_w
    cvt_split_kernel<<<N4_TOTAL / 256, 256>>>(x, qkv_w, out_w);

    // 1) QKV projection + fused RoPE -> q/k/v hi/lo
    gemm_bf16x3_kernel<1><<<dim3(QKVN / 128, BSROWS / 128), 256, GEMM_SMEM>>>(
        p_xhi, p_xlo, p_wqhi, p_wqlo, nullptr, pos, QKVN);

    // 2) Causal flash attention -> att hi/lo
    attn_tc_kernel<<<dim3(SS / 128, BB * HH), 256, ATT_SMEM>>>();

    // 3) Output projection -> fp32 out
    gemm_bf16x3_kernel<0><<<dim3(DM / 128, BSROWS / 128), 256, GEMM_SMEM>>>(
        p_ahi, p_alo, p_wohi, p_wolo, out, nullptr, DM);
}

// round 11
// speedup vs baseline: 3.6696x; 1.0390x over previous
#include <cuda_runtime.h>
#include <cuda_bf16.h>
#include <math.h>
#include <stdint.h>

#define BB 2
#define SS 2048
#define DM 1024
#define HH 16
#define DK 64
#define BSROWS (BB*SS)      // 4096
#define QKVN (3*DM)         // 3072

// ===========================================================================
// Scratch (allocation-free rule: __device__ globals). Everything bf16 hi/lo.
// ===========================================================================
__device__ __align__(16) __nv_bfloat16 x_hi[(size_t)BSROWS*DM];
__device__ __align__(16) __nv_bfloat16 x_lo[(size_t)BSROWS*DM];
__device__ __align__(16) __nv_bfloat16 wq_hi[(size_t)QKVN*DM];
__device__ __align__(16) __nv_bfloat16 wq_lo[(size_t)QKVN*DM];
__device__ __align__(16) __nv_bfloat16 wo_hi[(size_t)DM*DM];
__device__ __align__(16) __nv_bfloat16 wo_lo[(size_t)DM*DM];
__device__ __align__(16) __nv_bfloat16 q_hi[(size_t)BB*HH*SS*DK];
__device__ __align__(16) __nv_bfloat16 q_lo[(size_t)BB*HH*SS*DK];
__device__ __align__(16) __nv_bfloat16 k_hi[(size_t)BB*HH*SS*DK];
__device__ __align__(16) __nv_bfloat16 k_lo[(size_t)BB*HH*SS*DK];
__device__ __align__(16) __nv_bfloat16 v_hi[(size_t)BB*HH*SS*DK];
__device__ __align__(16) __nv_bfloat16 v_lo[(size_t)BB*HH*SS*DK];
__device__ __align__(16) __nv_bfloat16 att_hi[(size_t)BSROWS*DM];
__device__ __align__(16) __nv_bfloat16 att_lo[(size_t)BSROWS*DM];

// ===========================================================================
// PTX helpers
// ===========================================================================
__device__ __forceinline__ uint32_t smem_u32(const void* p) {
    uint32_t a;
    asm("{ .reg .u64 t; cvta.to.shared.u64 t, %1; cvt.u32.u64 %0, t; }" : "=r"(a) : "l"(p));
    return a;
}
__device__ __forceinline__ void ldsm_x4(uint32_t* r, uint32_t addr) {
    asm volatile("ldmatrix.sync.aligned.m8n8.x4.shared.b16 {%0,%1,%2,%3}, [%4];"
                 : "=r"(r[0]), "=r"(r[1]), "=r"(r[2]), "=r"(r[3]) : "r"(addr));
}
__device__ __forceinline__ void ldsm_x4t(uint32_t* r, uint32_t addr) {
    asm volatile("ldmatrix.sync.aligned.m8n8.x4.trans.shared.b16 {%0,%1,%2,%3}, [%4];"
                 : "=r"(r[0]), "=r"(r[1]), "=r"(r[2]), "=r"(r[3]) : "r"(addr));
}
__device__ __forceinline__ void mma16816(float* d, const uint32_t* a, const uint32_t* b) {
    asm volatile("mma.sync.aligned.m16n8k16.row.col.f32.bf16.bf16.f32 "
                 "{%0,%1,%2,%3}, {%4,%5,%6,%7}, {%8,%9}, {%0,%1,%2,%3};"
                 : "+f"(d[0]), "+f"(d[1]), "+f"(d[2]), "+f"(d[3])
                 : "r"(a[0]), "r"(a[1]), "r"(a[2]), "r"(a[3]), "r"(b[0]), "r"(b[1]));
}
__device__ __forceinline__ void cp16(uint32_t saddr, const void* g) {
    asm volatile("cp.async.cg.shared.global [%0], [%1], 16;" :: "r"(saddr), "l"(g));
}
#define CP_COMMIT() asm volatile("cp.async.commit_group;" ::: "memory")
#define CP_WAIT1()  asm volatile("cp.async.wait_group 1;" ::: "memory")
#define CP_WAIT0()  asm volatile("cp.async.wait_group 0;" ::: "memory")

__device__ __forceinline__ uint32_t bf2u(__nv_bfloat16 a, __nv_bfloat16 b) {
    __nv_bfloat162 t; t.x = a; t.y = b;
    return *reinterpret_cast<uint32_t*>(&t);
}
__device__ __forceinline__ void cvt_hl(float4 v, uint2& hi, uint2& lo) {
    __nv_bfloat16 h0 = __float2bfloat16_rn(v.x);
    __nv_bfloat16 h1 = __float2bfloat16_rn(v.y);
    __nv_bfloat16 h2 = __float2bfloat16_rn(v.z);
    __nv_bfloat16 h3 = __float2bfloat16_rn(v.w);
    __nv_bfloat16 l0 = __float2bfloat16_rn(v.x - __bfloat162float(h0));
    __nv_bfloat16 l1 = __float2bfloat16_rn(v.y - __bfloat162float(h1));
    __nv_bfloat16 l2 = __float2bfloat16_rn(v.z - __bfloat162float(h2));
    __nv_bfloat16 l3 = __float2bfloat16_rn(v.w - __bfloat162float(h3));
    hi = make_uint2(bf2u(h0, h1), bf2u(h2, h3));
    lo = make_uint2(bf2u(l0, l1), bf2u(l2, l3));
}
__device__ __forceinline__ void split2(float a, float b, uint32_t& hi, uint32_t& lo) {
    __nv_bfloat16 h0 = __float2bfloat16_rn(a);
    __nv_bfloat16 h1 = __float2bfloat16_rn(b);
    __nv_bfloat16 l0 = __float2bfloat16_rn(a - __bfloat162float(h0));
    __nv_bfloat16 l1 = __float2bfloat16_rn(b - __bfloat162float(h1));
    hi = bf2u(h0, h1);
    lo = bf2u(l0, l1);
}

// ===========================================================================
// Convert: split x / qkv_w / out_w fp32 -> bf16 hi/lo
// ===========================================================================
#define N4_X  (BSROWS*DM/4)
#define N4_WQ (QKVN*DM/4)
#define N4_WO (DM*DM/4)
#define N4_TOTAL (N4_X + N4_WQ + N4_WO)

__global__ __launch_bounds__(256)
void cvt_split_kernel(const float* __restrict__ x, const float* __restrict__ wq,
                      const float* __restrict__ wo) {
    int i = blockIdx.x * blockDim.x + threadIdx.x;
    const float4* s; uint2 *dh, *dl; int j;
    if (i < N4_X)                  { j = i;                 s = (const float4*)x;  dh = (uint2*)x_hi;  dl = (uint2*)x_lo; }
    else if (i < N4_X + N4_WQ)     { j = i - N4_X;          s = (const float4*)wq; dh = (uint2*)wq_hi; dl = (uint2*)wq_lo; }
    else                           { j = i - N4_X - N4_WQ;  s = (const float4*)wo; dh = (uint2*)wo_hi; dl = (uint2*)wo_lo; }
    float4 v = s[j];
    uint2 h, l;
    cvt_hl(v, h, l);
    dh[j] = h; dl[j] = l;
}

// ===========================================================================
// bf16x3 GEMM via mma.sync + cp.async. C[M,N] = A[M,1024] @ B[N,1024]^T.
// CTA tile 256x128, 512 threads (16 warps, 4m x 4n, warp tile 64x32),
// K-chunk 32, 3-stage cp.async ring, SINGLE barrier per chunk.
// MODE 0: store fp32 C. MODE 1: fused RoPE epilogue -> q/k/v hi/lo.
// ===========================================================================
#define KC 32
#define LDAS 40
#define OFF_AHI 0
#define OFF_ALO 20480                   // 256*40*2
#define OFF_BHI 40960
#define OFF_BLO 51200                   // +128*40*2
#define STAGE_B 61440
#define GEMM_SMEM (3*STAGE_B)           // 184320
#define KLOG 0.28782313662f             // 2/64 * ln(10000)

template<int MODE>
__global__ __launch_bounds__(512, 1)
void gemm_bf16x3_kernel(const __nv_bfloat16* __restrict__ Ahi, const __nv_bfloat16* __restrict__ Alo,
                        const __nv_bfloat16* __restrict__ Bhi, const __nv_bfloat16* __restrict__ Blo,
                        float* __restrict__ C, const int* __restrict__ pos, int N) {
    extern __shared__ char smem[];
    const uint32_t sbase = smem_u32(smem);
    const int tid  = threadIdx.x;
    const int wid  = tid >> 5;
    const int lane = tid & 31;
    const int m0 = blockIdx.y * 256;
    const int n0 = blockIdx.x * 128;
    const int wm = wid & 3;          // 0..3 -> m slab of 64
    const int wn = wid >> 2;         // 0..3 -> n slab of 32

    const uint4* Ah4 = (const uint4*)Ahi;
    const uint4* Al4 = (const uint4*)Alo;
    const uint4* Bh4 = (const uint4*)Bhi;
    const uint4* Bl4 = (const uint4*)Blo;

    // loader: A 256x32 (2 uint4/thread/array), B 128x32 (1 uint4/thread/array)
    auto issue = [&](int c, int s) {
        const int k0 = c * KC;
        const uint32_t sb0 = sbase + s * STAGE_B;
#pragma unroll
        for (int it = 0; it < 2; it++) {
            int f = it * 512 + tid;
            int row = f >> 2;
            int ch  = (f & 3) * 8;
            size_t gi = ((size_t)(m0 + row) * DM + k0 + ch) >> 3;
            uint32_t so = sb0 + (uint32_t)(row * LDAS + ch) * 2;
            cp16(so + OFF_AHI, Ah4 + gi);
            cp16(so + OFF_ALO, Al4 + gi);
        }
        {
            int row = tid >> 2;
            int ch  = (tid & 3) * 8;
            size_t gj = ((size_t)(n0 + row) * DM + k0 + ch) >> 3;
            uint32_t so = sb0 + (uint32_t)(row * LDAS + ch) * 2;
            cp16(so + OFF_BHI, Bh4 + gj);
            cp16(so + OFF_BLO, Bl4 + gj);
        }
    };

    // ldmatrix lane addressing
    const int gg   = lane >> 3;
    const int arow = (lane & 7) + ((lane >> 3) & 1) * 8;
    const int acol = (lane >> 4) * 8;
    const int b4row = ((gg >> 1) & 1) * 8 + (lane & 7);
    const int b4col = (gg & 1) * 8;

    float acc[4][4][4];
#pragma unroll
    for (int mi = 0; mi < 4; mi++)
#pragma unroll
        for (int ni = 0; ni < 4; ni++)
#pragma unroll
            for (int q = 0; q < 4; q++) acc[mi][ni][q] = 0.0f;

    const int nch = DM / KC;   // 32
    issue(0, 0); CP_COMMIT();
    issue(1, 1); CP_COMMIT();

    int stg_i = 0;
    for (int c = 0; c < nch; c++) {
        if (c + 1 < nch) CP_WAIT1(); else CP_WAIT0();
        __syncthreads();
        if (c + 2 < nch) { issue(c + 2, (stg_i + 2) % 3); CP_COMMIT(); }

        const uint32_t stg = sbase + stg_i * STAGE_B;
#pragma unroll
        for (int ks = 0; ks < 2; ks++) {
            uint32_t ah[4][4], al[4][4];
#pragma unroll
            for (int mi = 0; mi < 4; mi++) {
                uint32_t eoff = ((wm * 64 + mi * 16 + arow) * LDAS + ks * 16 + acol) * 2;
                ldsm_x4(ah[mi], stg + OFF_AHI + eoff);
                ldsm_x4(al[mi], stg + OFF_ALO + eoff);
            }
#pragma unroll
            for (int n2 = 0; n2 < 2; n2++) {
                uint32_t bhf[4], blf[4];
                uint32_t eoff = ((wn * 32 + n2 * 16 + b4row) * LDAS + ks * 16 + b4col) * 2;
                ldsm_x4(bhf, stg + OFF_BHI + eoff);
                ldsm_x4(blf, stg + OFF_BLO + eoff);
#pragma unroll
                for (int mi = 0; mi < 4; mi++) {
                    mma16816(acc[mi][n2 * 2],     ah[mi], bhf);
                    mma16816(acc[mi][n2 * 2],     ah[mi], blf);
                    mma16816(acc[mi][n2 * 2],     al[mi], bhf);
                    mma16816(acc[mi][n2 * 2 + 1], ah[mi], bhf + 2);
                    mma16816(acc[mi][n2 * 2 + 1], ah[mi], blf + 2);
                    mma16816(acc[mi][n2 * 2 + 1], al[mi], bhf + 2);
                }
            }
        }
        stg_i = (stg_i + 1) % 3;
    }

    const int crow = lane >> 2;
    const int ccol = (lane & 3) * 2;

    if (MODE == 0) {
#pragma unroll
        for (int mi = 0; mi < 4; mi++) {
            const size_t r0 = (size_t)(m0 + wm * 64 + mi * 16 + crow);
#pragma unroll
            for (int ni = 0; ni < 4; ni++) {
                const int cc = n0 + wn * 32 + ni * 8 + ccol;
                *(float2*)(C + r0 * N + cc)       = make_float2(acc[mi][ni][0], acc[mi][ni][1]);
                *(float2*)(C + (r0 + 8) * N + cc) = make_float2(acc[mi][ni][2], acc[mi][ni][3]);
            }
        }
    } else {
        const int sec  = n0 >> 10;
        const int nmod = n0 & 1023;
        int hh_[4], ii_[4];
        float ifr_[4];
#pragma unroll
        for (int ni = 0; ni < 4; ni++) {
            int colmod = nmod + wn * 32 + ni * 8 + ccol;
            hh_[ni] = colmod >> 6;
            ii_[ni] = (colmod & 63) >> 1;
            ifr_[ni] = (sec < 2) ? expf(-(float)ii_[ni] * KLOG) : 0.0f;
        }
        uint32_t* ghi = (sec == 0) ? (uint32_t*)q_hi : (sec == 1) ? (uint32_t*)k_hi : (uint32_t*)v_hi;
        uint32_t* glo = (sec == 0) ? (uint32_t*)q_lo : (sec == 1) ? (uint32_t*)k_lo : (uint32_t*)v_lo;
#pragma unroll
        for (int mi = 0; mi < 4; mi++) {
            const int rbase = m0 + wm * 64 + mi * 16 + crow;
#pragma unroll
            for (int half = 0; half < 2; half++) {
                const int r = rbase + half * 8;
                const int p = pos[r];
                const int b = r >> 11;
                const int s = r & 2047;
#pragma unroll
                for (int ni = 0; ni < 4; ni++) {
                    float v0 = acc[mi][ni][half * 2];
                    float v1 = acc[mi][ni][half * 2 + 1];
                    float o0, o1;
                    if (sec < 2) {
                        float ang = (float)p * ifr_[ni];
                        float cs = cosf(ang), sn = sinf(ang);
                        o0 = v0 * cs - v1 * sn;
                        o1 = v0 * sn + v1 * cs;
                        if (sec == 0) { o0 *= 0.125f; o1 *= 0.125f; }
                    } else { o0 = v0; o1 = v1; }
                    uint32_t hi, lo;
                    split2(o0, o1, hi, lo);
                    size_t idx = ((size_t)(b * HH + hh_[ni]) * SS + s) * 32 + ii_[ni];
                    ghi[idx] = hi;
                    glo[idx] = lo;
                }
            }
        }
    }
}

// ===========================================================================
// Tensor-core causal flash attention (bf16x3), pre-split q/k/v, 3-stage
// cp.async KV ring with SINGLE barrier per tile, x4 ldmatrix K/V.
// ===========================================================================
#define AT_LDS 72
#define AT_STG 36864                    // KV stage: Khi,Klo,Vhi,Vlo @ 9216
#define AT_QHI (3*AT_STG)               // 110592
#define AT_QLO (AT_QHI + 18432)
#define ATT_SMEM (AT_QLO + 18432)       // 147456

__global__ __launch_bounds__(256)
void attn_tc_kernel() {
    extern __shared__ char smem[];
    const uint32_t sb = smem_u32(smem);
    const int tid  = threadIdx.x;
    const int wid  = tid >> 5;
    const int lane = tid & 31;
    const int bh = blockIdx.y;
    const int qt = gridDim.x - 1 - blockIdx.x;   // heavy tiles first
    const int qbase = qt * 128;

    const uint4* qh4 = (const uint4*)q_hi + (size_t)bh * SS * 8;
    const uint4* ql4 = (const uint4*)q_lo + (size_t)bh * SS * 8;
    const uint4* kh4 = (const uint4*)k_hi + (size_t)bh * SS * 8;
    const uint4* kl4 = (const uint4*)k_lo + (size_t)bh * SS * 8;
    const uint4* vh4 = (const uint4*)v_hi + (size_t)bh * SS * 8;
    const uint4* vl4 = (const uint4*)v_lo + (size_t)bh * SS * 8;

    // ---- load Q tile 128x64 hi/lo ----
#pragma unroll
    for (int it = 0; it < 4; it++) {
        int f = it * 256 + tid;
        int row = f >> 3;
        int ch  = f & 7;
        uint32_t so = (uint32_t)(row * AT_LDS + ch * 8) * 2;
        *(uint4*)(smem + AT_QHI + so) = qh4[(size_t)(qbase + row) * 8 + ch];
        *(uint4*)(smem + AT_QLO + so) = ql4[(size_t)(qbase + row) * 8 + ch];
    }
    __syncthreads();

    const int gg   = lane >> 3;
    const int arow = (lane & 7) + ((lane >> 3) & 1) * 8;
    const int acol = (lane >> 4) * 8;
    const int b4row = ((gg >> 1) & 1) * 8 + (lane & 7);
    const int b4col = (gg & 1) * 8;
    const int v4row = (gg & 1) * 8 + (lane & 7);
    const int v4col = (gg >> 1) * 8;

    uint32_t qh[4][4], ql[4][4];
#pragma unroll
    for (int ks = 0; ks < 4; ks++) {
        uint32_t eoff = ((wid * 16 + arow) * AT_LDS + ks * 16 + acol) * 2;
        ldsm_x4(qh[ks], sb + AT_QHI + eoff);
        ldsm_x4(ql[ks], sb + AT_QLO + eoff);
    }

    float o[8][4];
#pragma unroll
    for (int ni = 0; ni < 8; ni++)
#pragma unroll
        for (int q = 0; q < 4; q++) o[ni][q] = 0.0f;
    float m0 = -INFINITY, m1 = -INFINITY, l0 = 0.0f, l1 = 0.0f;

    const int g  = lane >> 2;
    const int qq = lane & 3;
    const int row0 = qbase + wid * 16 + g;
    const int warp_maxrow = qbase + wid * 16 + 15;

    auto kv_issue = [&](int t, int s) {
        const int kvb = t * 64;
#pragma unroll
        for (int it = 0; it < 2; it++) {
            int f = it * 256 + tid;
            int row = f >> 3;
            int ch  = f & 7;
            uint32_t so = sb + s * AT_STG + (uint32_t)(row * AT_LDS + ch * 8) * 2;
            size_t gi = (size_t)(kvb + row) * 8 + ch;
            cp16(so,         kh4 + gi);
            cp16(so +  9216, kl4 + gi);
            cp16(so + 18432, vh4 + gi);
            cp16(so + 27648, vl4 + gi);
        }
    };

    const int ntiles = (qt + 1) * 2;
    kv_issue(0, 0); CP_COMMIT();
    if (ntiles > 1) { kv_issue(1, 1); CP_COMMIT(); }

    int stg_i = 0;
    for (int t = 0; t < ntiles; t++) {
        if (t + 1 < ntiles) CP_WAIT1(); else CP_WAIT0();
        __syncthreads();
        if (t + 2 < ntiles) { kv_issue(t + 2, (stg_i + 2) % 3); CP_COMMIT(); }

        const int kvb = t * 64;
        const uint32_t stg = sb + stg_i * AT_STG;

        if (kvb <= warp_maxrow) {
            // ---- S = Q @ K^T (3-term), K frags via x4 pairs ----
            float s[8][4];
#pragma unroll
            for (int ni = 0; ni < 8; ni++)
#pragma unroll
                for (int q = 0; q < 4; q++) s[ni][q] = 0.0f;
#pragma unroll
            for (int ks = 0; ks < 4; ks++) {
#pragma unroll
                for (int n2 = 0; n2 < 4; n2++) {
                    uint32_t khf[4], klf[4];
                    uint32_t eoff = ((n2 * 16 + b4row) * AT_LDS + ks * 16 + b4col) * 2;
                    ldsm_x4(khf, stg + eoff);
                    ldsm_x4(klf, stg + 9216 + eoff);
                    mma16816(s[n2 * 2],     qh[ks], khf);
                    mma16816(s[n2 * 2],     qh[ks], klf);
                    mma16816(s[n2 * 2],     ql[ks], khf);
                    mma16816(s[n2 * 2 + 1], qh[ks], khf + 2);
                    mma16816(s[n2 * 2 + 1], qh[ks], klf + 2);
                    mma16816(s[n2 * 2 + 1], ql[ks], khf + 2);
                }
            }

            // ---- causal mask ----
            if (kvb + 63 > qbase + wid * 16) {
#pragma unroll
                for (int ni = 0; ni < 8; ni++) {
                    int c = kvb + ni * 8 + qq * 2;
                    if (c     > row0)     s[ni][0] = -INFINITY;
                    if (c + 1 > row0)     s[ni][1] = -INFINITY;
                    if (c     > row0 + 8) s[ni][2] = -INFINITY;
                    if (c + 1 > row0 + 8) s[ni][3] = -INFINITY;
                }
            }

            // ---- online softmax ----
            float t0 = -INFINITY, t1 = -INFINITY;
#pragma unroll
            for (int ni = 0; ni < 8; ni++) {
                t0 = fmaxf(t0, fmaxf(s[ni][0], s[ni][1]));
                t1 = fmaxf(t1, fmaxf(s[ni][2], s[ni][3]));
            }
            t0 = fmaxf(t0, __shfl_xor_sync(0xFFFFFFFF, t0, 1));
            t0 = fmaxf(t0, __shfl_xor_sync(0xFFFFFFFF, t0, 2));
            t1 = fmaxf(t1, __shfl_xor_sync(0xFFFFFFFF, t1, 1));
            t1 = fmaxf(t1, __shfl_xor_sync(0xFFFFFFFF, t1, 2));
            float nm0 = fmaxf(m0, t0), nm1 = fmaxf(m1, t1);
            float sc0 = __expf(m0 - nm0), sc1 = __expf(m1 - nm1);
            m0 = nm0; m1 = nm1;
            l0 *= sc0; l1 *= sc1;
#pragma unroll
            for (int ni = 0; ni < 8; ni++) {
                o[ni][0] *= sc0; o[ni][1] *= sc0;
                o[ni][2] *= sc1; o[ni][3] *= sc1;
            }

            // ---- P = exp(S - m) -> bf16 hi/lo fragments ----
            uint32_t ph[8][2], pl[8][2];
            float rs0 = 0.0f, rs1 = 0.0f;
#pragma unroll
            for (int ni = 0; ni < 8; ni++) {
                float p0 = __expf(s[ni][0] - m0);
                float p1 = __expf(s[ni][1] - m0);
                float p2 = __expf(s[ni][2] - m1);
                float p3 = __expf(s[ni][3] - m1);
                rs0 += p0 + p1;
                rs1 += p2 + p3;
                split2(p0, p1, ph[ni][0], pl[ni][0]);
                split2(p2, p3, ph[ni][1], pl[ni][1]);
            }
            rs0 += __shfl_xor_sync(0xFFFFFFFF, rs0, 1);
            rs0 += __shfl_xor_sync(0xFFFFFFFF, rs0, 2);
            rs1 += __shfl_xor_sync(0xFFFFFFFF, rs1, 1);
            rs1 += __shfl_xor_sync(0xFFFFFFFF, rs1, 2);
            l0 += rs0; l1 += rs1;

            // ---- O += P @ V (3-term); V frags via x4.trans pairs ----
#pragma unroll
            for (int kc = 0; kc < 4; kc++) {
                uint32_t ah[4] = { ph[2*kc][0], ph[2*kc][1], ph[2*kc+1][0], ph[2*kc+1][1] };
                uint32_t al[4] = { pl[2*kc][0], pl[2*kc][1], pl[2*kc+1][0], pl[2*kc+1][1] };
#pragma unroll
                for (int n2 = 0; n2 < 4; n2++) {
                    uint32_t vhf[4], vlf[4];
                    uint32_t eoff = ((kc * 16 + v4row) * AT_LDS + n2 * 16 + v4col) * 2;
                    ldsm_x4t(vhf, stg + 18432 + eoff);
                    ldsm_x4t(vlf, stg + 27648 + eoff);
                    mma16816(o[n2 * 2],     ah, vhf);
                    mma16816(o[n2 * 2],     ah, vlf);
                    mma16816(o[n2 * 2],     al, vhf);
                    mma16816(o[n2 * 2 + 1], ah, vhf + 2);
                    mma16816(o[n2 * 2 + 1], ah, vlf + 2);
                    mma16816(o[n2 * 2 + 1], al, vhf + 2);
                }
            }
        }
        stg_i = (stg_i + 1) % 3;
    }

    // ---- epilogue: normalize + split -> att_hi/att_lo ----
    const float inv0 = 1.0f / l0;
    const float inv1 = 1.0f / l1;
    const int b = bh / HH;
    const int h = bh % HH;
    uint32_t* ahi32 = (uint32_t*)att_hi;
    uint32_t* alo32 = (uint32_t*)att_lo;
    const size_t base0 = ((size_t)b * SS + row0) * 512 + h * 32;
    const size_t base1 = ((size_t)b * SS + row0 + 8) * 512 + h * 32;
#pragma unroll
    for (int ni = 0; ni < 8; ni++) {
        uint32_t hi, lo;
        split2(o[ni][0] * inv0, o[ni][1] * inv0, hi, lo);
        ahi32[base0 + ni * 4 + qq] = hi;
        alo32[base0 + ni * 4 + qq] = lo;
        split2(o[ni][2] * inv1, o[ni][3] * inv1, hi, lo);
        ahi32[base1 + ni * 4 + qq] = hi;
        alo32[base1 + ni * 4 + qq] = lo;
    }
}

// ===========================================================================
extern "C" void kernel_launch(void* const* d_in, const int* in_sizes, int n_in,
                              void* d_out, int out_size) {
    const float* x     = (const float*)d_in[0];
    const int*   pos   = (const int*)d_in[1];
    const float* qkv_w = (const float*)d_in[2];
    const float* out_w = (const float*)d_in[3];
    float* out = (float*)d_out;

    __nv_bfloat16 *p_xhi, *p_xlo, *p_wqhi, *p_wqlo, *p_wohi, *p_wolo, *p_ahi, *p_alo;
    cudaGetSymbolAddress((void**)&p_xhi,  x_hi);
    cudaGetSymbolAddress((void**)&p_xlo,  x_lo);
    cudaGetSymbolAddress((void**)&p_wqhi, wq_hi);
    cudaGetSymbolAddress((void**)&p_wqlo, wq_lo);
    cudaGetSymbolAddress((void**)&p_wohi, wo_hi);
    cudaGetSymbolAddress((void**)&p_wolo, wo_lo);
    cudaGetSymbolAddress((void**)&p_ahi,  att_hi);
    cudaGetSymbolAddress((void**)&p_alo,  att_lo);

    cudaFuncSetAttribute(gemm_bf16x3_kernel<0>, cudaFuncAttributeMaxDynamicSharedMemorySize, GEMM_SMEM);
    cudaFuncSetAttribute(gemm_bf16x3_kernel<1>, cudaFuncAttributeMaxDynamicSharedMemorySize, GEMM_SMEM);
    cudaFuncSetAttribute(attn_tc_kernel,        cudaFuncAttributeMaxDynamicSharedMemorySize, ATT_SMEM);

    // 0) fp32 -> bf16 hi/lo for x, qkv_w, out_w
    cvt_split_kernel<<<N4_TOTAL / 256, 256>>>(x, qkv_w, out_w);

    // 1) QKV projection + fused RoPE -> q/k/v hi/lo
    gemm_bf16x3_kernel<1><<<dim3(QKVN / 128, BSROWS / 256), 512, GEMM_SMEM>>>(
        p_xhi, p_xlo, p_wqhi, p_wqlo, nullptr, pos, QKVN);

    // 2) Causal flash attention -> att hi/lo
    attn_tc_kernel<<<dim3(SS / 128, BB * HH), 256, ATT_SMEM>>>();

    // 3) Output projection -> fp32 out
    gemm_bf16x3_kernel<0><<<dim3(DM / 128, BSROWS / 256), 512, GEMM_SMEM>>>(
        p_ahi, p_alo, p_wohi, p_wolo, out, nullptr, DM);
}